// round 6
// baseline (speedup 1.0000x reference)
#include <cuda_runtime.h>
#include <cuda_fp16.h>
#include <cstdint>

// Problem dims (fixed)
#define NB   8
#define LQ   1024
#define SSEQ 4096
#define DD   512

// tcgen05 is an arch-specific ('a') feature: only emit it in device passes that
// target sm_103a/sm_100a-class specifics. The plain compute_103 pass gets a
// correct mma.sync fallback so ptxas never sees tcgen05 text.
#ifndef __CUDA_ARCH_SPECIFIC__
#define __CUDA_ARCH_SPECIFIC__ 0
#endif
#if defined(__CUDA_ARCH_FEAT_SM103_ALL) || defined(__CUDA_ARCH_FEAT_SM100_ALL) || (__CUDA_ARCH_SPECIFIC__ >= 1000)
#define HAS_TCGEN05 1
#else
#define HAS_TCGEN05 0
#endif

// ---------------- static device scratch (no allocations allowed) ----------------
static __device__ float g_q  [NB * LQ * DD];
static __device__ float g_k  [NB * SSEQ * DD];
static __device__ float g_vT [NB * DD * SSEQ];        // v transposed: [b][d][s]
static __device__ float g_q2 [NB * LQ];
static __device__ float g_k2 [NB * SSEQ];
static __device__ float g_s  [NB * LQ * SSEQ];        // scores -> attn in place
static __device__ float g_msg[NB * LQ * DD];
static __device__ float g_mw [NB * LQ * DD];
static __device__ float g_mln[NB * LQ * DD];
static __device__ float g_hid[NB * LQ * 2 * DD];
static __device__ float g_ffn[NB * LQ * DD];
static __device__ float g_wt [4 * DD * DD + 2 * DD * 2 * DD + 2 * DD * DD];

// ======================= PTX helpers =======================
__device__ __forceinline__ uint32_t smem_u32(const void* p) {
    uint32_t a;
    asm("{ .reg .u64 t; cvta.to.shared.u64 t, %1; cvt.u32.u64 %0, t; }" : "=r"(a) : "l"(p));
    return a;
}
__device__ __forceinline__ float to_tf32(float x) {
    float r;
    asm("cvt.rna.tf32.f32 %0, %1;" : "=f"(r) : "f"(x));
    return r;
}

#if HAS_TCGEN05
__device__ __forceinline__ uint32_t elect_one() {
    uint32_t pred;
    asm volatile("{\n\t.reg .pred p;\n\telect.sync _|p, 0xFFFFFFFF;\n\t"
                 "selp.b32 %0, 1, 0, p;\n\t}" : "=r"(pred));
    return pred;
}
#define MBAR_INIT(addr, cnt) \
    asm volatile("mbarrier.init.shared.b64 [%0], %1;" :: "r"(addr), "r"(cnt) : "memory")
#define MBAR_INVAL(addr) \
    asm volatile("mbarrier.inval.shared.b64 [%0];" :: "r"(addr) : "memory")
__device__ __forceinline__ void mbar_wait(uint32_t addr, uint32_t parity) {
    uint32_t done;
    asm volatile("{\n\t.reg .pred p;\n\t"
                 "mbarrier.try_wait.parity.acquire.cta.shared::cta.b64 p, [%1], %2;\n\t"
                 "selp.b32 %0, 1, 0, p;\n\t}" : "=r"(done) : "r"(addr), "r"(parity) : "memory");
    if (!done) {
        asm volatile("{\n\t.reg .pred P1;\n\t"
                     "W_%=:\n\t"
                     "mbarrier.try_wait.parity.acquire.cta.shared::cta.b64 P1, [%0], %1, 0x989680;\n\t"
                     "@P1 bra.uni D_%=;\n\t"
                     "bra.uni W_%=;\n\t"
                     "D_%=:\n\t}" :: "r"(addr), "r"(parity) : "memory");
    }
}
#define TC_ALLOC(smem_addr, n) \
    asm volatile("tcgen05.alloc.cta_group::1.sync.aligned.shared::cta.b32 [%0], %1;" \
                 :: "r"(smem_addr), "r"(n) : "memory")
#define TC_DEALLOC(tmem, n) \
    asm volatile("tcgen05.dealloc.cta_group::1.sync.aligned.b32 %0, %1;" :: "r"(tmem), "r"(n))
#define TC_RELINQ() \
    asm volatile("tcgen05.relinquish_alloc_permit.cta_group::1.sync.aligned;")
#define TC_COMMIT(mbar) \
    asm volatile("tcgen05.commit.cta_group::1.mbarrier::arrive::one.shared::cluster.b64 [%0];" \
                 :: "r"(mbar) : "memory")
#define TC_FENCE_AFTER() asm volatile("tcgen05.fence::after_thread_sync;" ::: "memory")
#define TC_WAIT_LD()     asm volatile("tcgen05.wait::ld.sync.aligned;" ::: "memory")
#define FENCE_ASYNC()    asm volatile("fence.proxy.async.shared::cta;" ::: "memory")

__device__ __forceinline__ void mma_tf32_ss(uint32_t d, uint64_t a, uint64_t b,
                                            uint32_t idesc, uint32_t en) {
    asm volatile("{\n\t.reg .pred p;\n\tsetp.ne.u32 p, %4, 0;\n\t"
                 "tcgen05.mma.cta_group::1.kind::tf32 [%0], %1, %2, %3, {%5,%5,%5,%5}, p;\n\t}"
                 :: "r"(d), "l"(a), "l"(b), "r"(idesc), "r"(en), "r"(0u) : "memory");
}
__device__ __forceinline__ void tmem_ld_x32(uint32_t* r, uint32_t addr) {
    asm volatile(
        "tcgen05.ld.sync.aligned.32x32b.x32.b32 "
        "{%0,%1,%2,%3,%4,%5,%6,%7,%8,%9,%10,%11,%12,%13,%14,%15,"
        "%16,%17,%18,%19,%20,%21,%22,%23,%24,%25,%26,%27,%28,%29,%30,%31}, [%32];"
        : "=r"(r[0]), "=r"(r[1]), "=r"(r[2]), "=r"(r[3]), "=r"(r[4]), "=r"(r[5]),
          "=r"(r[6]), "=r"(r[7]), "=r"(r[8]), "=r"(r[9]), "=r"(r[10]), "=r"(r[11]),
          "=r"(r[12]), "=r"(r[13]), "=r"(r[14]), "=r"(r[15]), "=r"(r[16]), "=r"(r[17]),
          "=r"(r[18]), "=r"(r[19]), "=r"(r[20]), "=r"(r[21]), "=r"(r[22]), "=r"(r[23]),
          "=r"(r[24]), "=r"(r[25]), "=r"(r[26]), "=r"(r[27]), "=r"(r[28]), "=r"(r[29]),
          "=r"(r[30]), "=r"(r[31])
        : "r"(addr));
}
// SW128 swizzle on byte offsets (Swizzle<3,4,3>)
__device__ __forceinline__ uint32_t sw128(uint32_t b) { return b ^ ((b >> 3) & 0x70); }
// SMEM descriptor: SW128, version 1 (Blackwell), LBO=1, SBO=64
static __device__ __forceinline__ uint64_t make_desc(uint32_t addr) {
    const uint64_t base = (uint64_t(2) << 61) | (uint64_t(1) << 46)
                        | (uint64_t(64) << 32) | (uint64_t(1) << 16);
    return base | ((uint64_t)(addr >> 4) & 0x3FFF);
}
// idesc: D=F32, A=B=TF32 K-major, M=128, N=128
#define IDESC_TF32 ((1u << 4) | (2u << 7) | (2u << 10) | ((128u / 8u) << 17) | ((128u / 16u) << 24))
#endif  // HAS_TCGEN05

// ======================================================================
// NT GEMM: C[M,N] = A[M,K] * Bt[N,K]^T, fp32 accumulate, 128x128 CTA tile.
// sm_103a pass: tcgen05 tf32 SS pipeline:
//   - 4-slot smem ring (4 x 32KB), one mbarrier per slot
//   - register prefetch distance 1 (LDG for stage s+1 issued at top of stage s)
//   - one elected thread issues 4 K=8 MMAs + commit per stage
// other passes: fp16 mma.sync fallback (correct, slower; never runs on GB300).
// EPI: 0 none, 1 dist sqrt(max(rn[r]+cn[c]-2acc,0)), 2 relu.
// DUAL: A logical K = 2*512, first half gA, second gA2 (both lda=512).
// ======================================================================
template<int EPI, int DUAL>
__global__ __launch_bounds__(256)
void tc_gemm(const float* __restrict__ gA, const float* __restrict__ gA2,
             const float* __restrict__ gB, float* __restrict__ gC,
             int N, int K, int lda, int ldb,
             long long sA, long long sB, long long sC,
             const float* __restrict__ rn, const float* __restrict__ cn)
{
    extern __shared__ __align__(1024) char dyn_smem[];

    const int tid = threadIdx.x;
    const int wid = tid >> 5, lane = tid & 31;

    const long long z = blockIdx.z;
    const float* Abase  = gA + z * sA + (long long)blockIdx.y * 128 * lda;
    const float* A2base = DUAL ? (gA2 + (long long)blockIdx.y * 128 * lda) : nullptr;
    const float* Bbase  = gB + z * sB + (long long)blockIdx.x * 128 * ldb;
    float* Cbase = gC + z * sC + (long long)blockIdx.y * 128 * N + blockIdx.x * 128;

#if HAS_TCGEN05
    // ------------------------- tcgen05 path -------------------------
    __shared__ uint32_t s_tmem[1];
    __shared__ __align__(8) uint64_t s_mbar[4];

    const uint32_t smem_base = smem_u32(dyn_smem);
    uint32_t mbar[4];
#pragma unroll
    for (int i = 0; i < 4; i++) mbar[i] = smem_u32(&s_mbar[i]);

    if (wid == 0) {
        TC_ALLOC(smem_u32(s_tmem), 128);
        TC_RELINQ();
    }
    if (tid == 0) {
#pragma unroll
        for (int i = 0; i < 4; i++) MBAR_INIT(mbar[i], 1);
    }
    __syncthreads();
    const uint32_t tmem = s_tmem[0];

    // loader geometry: tile = 128 rows x 32 floats (128B rows, SW128)
    const int r0 = tid >> 3, c0 = tid & 7;

    float4 pa[2][4], pb[2][4];
    auto load_regs = [&](int s, int set) {
        const int k0 = s * 32;
        const float* Ap = DUAL ? (k0 < 512 ? Abase + k0 : A2base + (k0 - 512)) : (Abase + k0);
        const float* Bp = Bbase + k0;
#pragma unroll
        for (int j = 0; j < 4; j++) {
            int row = r0 + j * 32;
            pa[set][j] = *(const float4*)(Ap + (long long)row * lda + c0 * 4);
            pb[set][j] = *(const float4*)(Bp + (long long)row * ldb + c0 * 4);
        }
    };
    auto store_tile = [&](int slot, int set) {
        char* aB = dyn_smem + slot * 32768;
        char* bB = aB + 16384;
#pragma unroll
        for (int j = 0; j < 4; j++) {
            int row = r0 + j * 32;
            uint32_t off = sw128((uint32_t)(row * 128 + c0 * 16));
            float4 ta, tb;
            ta.x = to_tf32(pa[set][j].x); ta.y = to_tf32(pa[set][j].y);
            ta.z = to_tf32(pa[set][j].z); ta.w = to_tf32(pa[set][j].w);
            tb.x = to_tf32(pb[set][j].x); tb.y = to_tf32(pb[set][j].y);
            tb.z = to_tf32(pb[set][j].z); tb.w = to_tf32(pb[set][j].w);
            *(float4*)(aB + off) = ta;
            *(float4*)(bB + off) = tb;
        }
    };

    const int nst = K / 32;
    load_regs(0, 0);
    for (int s = 0; s < nst; s++) {
        const int set  = s & 1;
        const int slot = s & 3;
        const int rnd  = s >> 2;
        // prefetch next stage's operands first: LDG latency overlaps this stage
        if (s + 1 < nst) load_regs(s + 1, set ^ 1);
        // slot reuse guard: MMA of stage s-4 (commit #rnd-1 on this slot) must be done
        if (rnd >= 1) mbar_wait(mbar[slot], (rnd - 1) & 1);
        store_tile(slot, set);
        __syncthreads();
        if (wid == 0) {
            FENCE_ASYNC();
            if (elect_one()) {
                uint32_t aAddr = smem_base + slot * 32768;
                uint64_t ad = make_desc(aAddr);
                uint64_t bd = make_desc(aAddr + 16384);
#pragma unroll
                for (int st = 0; st < 4; st++)
                    mma_tf32_ss(tmem, ad + st * 2, bd + st * 2, IDESC_TF32,
                                (s > 0 || st > 0) ? 1u : 0u);
                TC_COMMIT(mbar[slot]);
            }
        }
    }
    {   // drain: last commit tracks ALL prior MMAs of this CTA
        const int L = nst - 1;
        mbar_wait(mbar[L & 3], (L >> 2) & 1);
    }
    TC_FENCE_AFTER();

    // epilogue: TMEM -> regs -> smem (coalesce) -> gmem
    float* stg = (float*)dyn_smem;                      // [128][33] staging
    const int Mtot = gridDim.y * 128;
    float rv = 0.0f, cnv = 0.0f;
    if (EPI == 1 && wid < 4)
        rv = rn[z * Mtot + (long long)blockIdx.y * 128 + wid * 32 + lane];

#pragma unroll
    for (int ch = 0; ch < 4; ch++) {
        if (wid < 4) {
            uint32_t r[32];
            tmem_ld_x32(r, tmem + ch * 32);
            TC_WAIT_LD();
            if (EPI == 1) cnv = cn[z * N + (long long)blockIdx.x * 128 + ch * 32 + lane];
            int row = wid * 32 + lane;
#pragma unroll
            for (int c = 0; c < 32; c++) {
                float v = __uint_as_float(r[c]);
                if (EPI == 1) {
                    float cc = __shfl_sync(0xffffffffu, cnv, c);
                    v = sqrtf(fmaxf(rv + cc - 2.0f * v, 0.0f));
                } else if (EPI == 2) {
                    v = fmaxf(v, 0.0f);
                }
                stg[row * 33 + c] = v;
            }
        }
        __syncthreads();
#pragma unroll
        for (int it = 0; it < 16; it++) {
            int row = wid + it * 8;
            Cbase[(long long)row * N + ch * 32 + lane] = stg[row * 33 + lane];
        }
        __syncthreads();
    }

    if (tid == 0) {
#pragma unroll
        for (int i = 0; i < 4; i++) MBAR_INVAL(mbar[i]);
    }
    __syncthreads();
    if (wid == 0) TC_DEALLOC(tmem, 128);

#else
    // ------------------------- fp16 mma.sync fallback -------------------------
    __half* As = (__half*)dyn_smem;                 // [2][128*40]
    __half* Bs = (__half*)dyn_smem + 2 * 128 * 40;  // [2][128*40]

    const int gid = lane >> 2, ctig = lane & 3;
    const int wm = (wid & 1) * 64;
    const int wn = (wid >> 1) * 32;
    const int aRow = tid >> 1;
    const int aOff = (tid & 1) * 16;

    float4 pa[4], pb[4];
    auto loadA = [&](int k0) {
        const float* Ap = DUAL ? (k0 < 512 ? Abase + k0 : A2base + (k0 - 512)) : (Abase + k0);
        const float* r = Ap + (long long)aRow * lda + aOff;
#pragma unroll
        for (int j = 0; j < 4; j++) pa[j] = *(const float4*)(r + 4 * j);
    };
    auto loadB = [&](int k0) {
        const float* r = Bbase + (long long)aRow * ldb + k0 + aOff;
#pragma unroll
        for (int j = 0; j < 4; j++) pb[j] = *(const float4*)(r + 4 * j);
    };
    auto storeAB = [&](int buf) {
        __half* Ab = As + buf * 128 * 40;
        __half* Bb = Bs + buf * 128 * 40;
#pragma unroll
        for (int j = 0; j < 4; j++) {
            *(__half2*)&Ab[aRow * 40 + aOff + 4 * j]     = __floats2half2_rn(pa[j].x, pa[j].y);
            *(__half2*)&Ab[aRow * 40 + aOff + 4 * j + 2] = __floats2half2_rn(pa[j].z, pa[j].w);
            *(__half2*)&Bb[aRow * 40 + aOff + 4 * j]     = __floats2half2_rn(pb[j].x, pb[j].y);
            *(__half2*)&Bb[aRow * 40 + aOff + 4 * j + 2] = __floats2half2_rn(pb[j].z, pb[j].w);
        }
    };

    float c[4][4][4];
#pragma unroll
    for (int mi = 0; mi < 4; mi++)
#pragma unroll
        for (int ni = 0; ni < 4; ni++)
#pragma unroll
            for (int r = 0; r < 4; r++) c[mi][ni][r] = 0.0f;

    loadA(0); loadB(0);
    storeAB(0);
    __syncthreads();

    const int nst = K / 32;
    for (int s = 0; s < nst; s++) {
        const int buf = s & 1;
        const __half* Ab = As + buf * 128 * 40;
        const __half* Bb = Bs + buf * 128 * 40;
        if (s + 1 < nst) { loadA((s + 1) * 32); loadB((s + 1) * 32); }
#pragma unroll
        for (int ks = 0; ks < 2; ks++) {
            const int kb = ks * 16;
            unsigned a[4][4], b[4][2];
#pragma unroll
            for (int mi = 0; mi < 4; mi++) {
                int r0 = wm + mi * 16 + gid;
                a[mi][0] = *(const unsigned*)&Ab[r0 * 40 + kb + 2 * ctig];
                a[mi][1] = *(const unsigned*)&Ab[(r0 + 8) * 40 + kb + 2 * ctig];
                a[mi][2] = *(const unsigned*)&Ab[r0 * 40 + kb + 8 + 2 * ctig];
                a[mi][3] = *(const unsigned*)&Ab[(r0 + 8) * 40 + kb + 8 + 2 * ctig];
            }
#pragma unroll
            for (int ni = 0; ni < 4; ni++) {
                int cc = wn + ni * 8 + gid;
                b[ni][0] = *(const unsigned*)&Bb[cc * 40 + kb + 2 * ctig];
                b[ni][1] = *(const unsigned*)&Bb[cc * 40 + kb + 8 + 2 * ctig];
            }
#pragma unroll
            for (int mi = 0; mi < 4; mi++)
#pragma unroll
                for (int ni = 0; ni < 4; ni++) {
                    asm volatile(
                        "mma.sync.aligned.m16n8k16.row.col.f32.f16.f16.f32 "
                        "{%0,%1,%2,%3}, {%4,%5,%6,%7}, {%8,%9}, {%0,%1,%2,%3};\n"
                        : "+f"(c[mi][ni][0]), "+f"(c[mi][ni][1]),
                          "+f"(c[mi][ni][2]), "+f"(c[mi][ni][3])
                        : "r"(a[mi][0]), "r"(a[mi][1]), "r"(a[mi][2]), "r"(a[mi][3]),
                          "r"(b[ni][0]), "r"(b[ni][1]));
                }
        }
        if (s + 1 < nst) storeAB(buf ^ 1);
        __syncthreads();
    }

    const int Mtot = gridDim.y * 128;
    const float* rnp = (EPI == 1) ? (rn + z * Mtot + (long long)blockIdx.y * 128) : nullptr;
    const float* cnp = (EPI == 1) ? (cn + z * N + blockIdx.x * 128) : nullptr;
#pragma unroll
    for (int mi = 0; mi < 4; mi++) {
#pragma unroll
        for (int half = 0; half < 2; half++) {
            int r = wm + mi * 16 + gid + half * 8;
            float rvv = (EPI == 1) ? rnp[r] : 0.0f;
#pragma unroll
            for (int ni = 0; ni < 4; ni++) {
                int cc = wn + ni * 8 + 2 * ctig;
                float v0 = c[mi][ni][half * 2 + 0];
                float v1 = c[mi][ni][half * 2 + 1];
                if (EPI == 1) {
                    v0 = sqrtf(fmaxf(rvv + cnp[cc]     - 2.0f * v0, 0.0f));
                    v1 = sqrtf(fmaxf(rvv + cnp[cc + 1] - 2.0f * v1, 0.0f));
                } else if (EPI == 2) {
                    v0 = fmaxf(v0, 0.0f);
                    v1 = fmaxf(v1, 0.0f);
                }
                *(float2*)(Cbase + (long long)r * N + cc) = make_float2(v0, v1);
            }
        }
    }
#endif
}

// ---------------- reductions ----------------
__device__ __forceinline__ float warpReduceSum(float v) {
    v += __shfl_xor_sync(0xffffffffu, v, 16);
    v += __shfl_xor_sync(0xffffffffu, v, 8);
    v += __shfl_xor_sync(0xffffffffu, v, 4);
    v += __shfl_xor_sync(0xffffffffu, v, 2);
    v += __shfl_xor_sync(0xffffffffu, v, 1);
    return v;
}
__device__ __forceinline__ float warpReduceMax(float v) {
    v = fmaxf(v, __shfl_xor_sync(0xffffffffu, v, 16));
    v = fmaxf(v, __shfl_xor_sync(0xffffffffu, v, 8));
    v = fmaxf(v, __shfl_xor_sync(0xffffffffu, v, 4));
    v = fmaxf(v, __shfl_xor_sync(0xffffffffu, v, 2));
    v = fmaxf(v, __shfl_xor_sync(0xffffffffu, v, 1));
    return v;
}
__device__ __forceinline__ float blockAllReduceSum(float v, float* sh) {
    int lane = threadIdx.x & 31, wid = threadIdx.x >> 5;
    v = warpReduceSum(v);
    if (lane == 0) sh[wid] = v;
    __syncthreads();
    int nw = blockDim.x >> 5;
    float t = (lane < nw) ? sh[lane] : 0.0f;
    t = warpReduceSum(t);
    __syncthreads();
    return t;
}
__device__ __forceinline__ float blockAllReduceMax(float v, float* sh) {
    int lane = threadIdx.x & 31, wid = threadIdx.x >> 5;
    v = warpReduceMax(v);
    if (lane == 0) sh[wid] = v;
    __syncthreads();
    int nw = blockDim.x >> 5;
    float t = (lane < nw) ? sh[lane] : -3.0e38f;
    t = warpReduceMax(t);
    __syncthreads();
    return t;
}

// ---------------- fp32 transpose (R,C multiples of 32): out[C,R] = in[R,C]^T ----
__global__ __launch_bounds__(256)
void transpose_kernel(const float* __restrict__ in, float* __restrict__ out,
                      int R, int C)
{
    __shared__ float t[32][33];
    int bx = blockIdx.x * 32, by = blockIdx.y * 32;
    int x = bx + threadIdx.x;
#pragma unroll
    for (int j = 0; j < 32; j += 8)
        t[threadIdx.y + j][threadIdx.x] = in[(long long)(by + threadIdx.y + j) * C + x];
    __syncthreads();
    int x2 = by + threadIdx.x;
#pragma unroll
    for (int j = 0; j < 32; j += 8)
        out[(long long)(bx + threadIdx.y + j) * R + x2] = t[threadIdx.x][threadIdx.y + j];
}

// ---------------- row squared-norm ----------------
__global__ __launch_bounds__(128)
void rownorm2_kernel(const float* __restrict__ X, float* __restrict__ out)
{
    __shared__ float sh[32];
    long long row = blockIdx.x;
    const float* x = X + row * DD;
    float4 v = *(const float4*)(x + threadIdx.x * 4);
    float s = v.x * v.x + v.y * v.y + v.z * v.z + v.w * v.w;
    s = blockAllReduceSum(s, sh);
    if (threadIdx.x == 0) out[row] = s;
}

// ---------------- softmax over S=4096, in place on g_s ----------------
__global__ __launch_bounds__(256)
void softmax_rows_kernel()
{
    __shared__ float sh[32];
    long long row = blockIdx.x;
    float* p = g_s + row * SSEQ;
    int t = threadIdx.x;

    float4 f[4];
    float mx = -3.0e38f;
#pragma unroll
    for (int i = 0; i < 4; i++) {
        f[i] = *(const float4*)(p + i * 1024 + t * 4);
        mx = fmaxf(mx, fmaxf(fmaxf(f[i].x, f[i].y), fmaxf(f[i].z, f[i].w)));
    }
    mx = blockAllReduceMax(mx, sh);

    float sum = 0.0f;
#pragma unroll
    for (int i = 0; i < 4; i++) {
        f[i].x = __expf(f[i].x - mx);
        f[i].y = __expf(f[i].y - mx);
        f[i].z = __expf(f[i].z - mx);
        f[i].w = __expf(f[i].w - mx);
        sum += f[i].x + f[i].y + f[i].z + f[i].w;
    }
    sum = blockAllReduceSum(sum, sh);
    float r = 1.0f / sum;
#pragma unroll
    for (int i = 0; i < 4; i++) {
        f[i].x *= r; f[i].y *= r; f[i].z *= r; f[i].w *= r;
        *(float4*)(p + i * 1024 + t * 4) = f[i];
    }
}

// ---------------- LayerNorm over D=512 (+ optional residual) ----------------
__global__ __launch_bounds__(128)
void layernorm_kernel(const float* __restrict__ X, const float* __restrict__ G,
                      const float* __restrict__ Bv, const float* __restrict__ R,
                      float* __restrict__ O)
{
    __shared__ float sh[32];
    long long row = blockIdx.x;
    int c = threadIdx.x * 4;
    float4 v = *(const float4*)(X + row * DD + c);

    float s = v.x + v.y + v.z + v.w;
    s = blockAllReduceSum(s, sh);
    float mu = s * (1.0f / DD);

    float d0 = v.x - mu, d1 = v.y - mu, d2 = v.z - mu, d3 = v.w - mu;
    float s2 = d0 * d0 + d1 * d1 + d2 * d2 + d3 * d3;
    s2 = blockAllReduceSum(s2, sh);
    float inv = rsqrtf(s2 * (1.0f / DD) + 1e-5f);

    float4 gg = *(const float4*)(G + c);
    float4 bb = *(const float4*)(Bv + c);
    float4 o;
    o.x = d0 * inv * gg.x + bb.x;
    o.y = d1 * inv * gg.y + bb.y;
    o.z = d2 * inv * gg.z + bb.z;
    o.w = d3 * inv * gg.w + bb.w;
    if (R) {
        float4 rr = *(const float4*)(R + row * DD + c);
        o.x += rr.x; o.y += rr.y; o.z += rr.z; o.w += rr.w;
    }
    *(float4*)(O + row * DD + c) = o;
}

// ======================================================================
#define SMEM_BYTES 131072

extern "C" void kernel_launch(void* const* d_in, const int* in_sizes, int n_in,
                              void* d_out, int out_size)
{
    (void)in_sizes; (void)n_in; (void)out_size;
    const float* x   = (const float*)d_in[0];
    const float* src = (const float*)d_in[1];
    const float* Wq  = (const float*)d_in[2];
    const float* Wk  = (const float*)d_in[3];
    const float* Wv  = (const float*)d_in[4];
    const float* Wm  = (const float*)d_in[5];
    const float* W1  = (const float*)d_in[6];
    const float* W2  = (const float*)d_in[7];
    const float* g1  = (const float*)d_in[8];
    const float* b1  = (const float*)d_in[9];
    const float* g2  = (const float*)d_in[10];
    const float* b2  = (const float*)d_in[11];
    float* out = (float*)d_out;

    float *q, *k, *vT, *q2, *k2, *sc, *msg, *mw, *mln, *hid, *ffn, *wt;
    cudaGetSymbolAddress((void**)&q,   g_q);
    cudaGetSymbolAddress((void**)&k,   g_k);
    cudaGetSymbolAddress((void**)&vT,  g_vT);
    cudaGetSymbolAddress((void**)&q2,  g_q2);
    cudaGetSymbolAddress((void**)&k2,  g_k2);
    cudaGetSymbolAddress((void**)&sc,  g_s);
    cudaGetSymbolAddress((void**)&msg, g_msg);
    cudaGetSymbolAddress((void**)&mw,  g_mw);
    cudaGetSymbolAddress((void**)&mln, g_mln);
    cudaGetSymbolAddress((void**)&hid, g_hid);
    cudaGetSymbolAddress((void**)&ffn, g_ffn);
    cudaGetSymbolAddress((void**)&wt,  g_wt);

    float* WqT = wt;
    float* WkT = wt + DD * DD;
    float* WvT = wt + 2 * DD * DD;
    float* WmT = wt + 3 * DD * DD;
    float* W1T = wt + 4 * DD * DD;
    float* W2T = wt + 8 * DD * DD;

    cudaFuncSetAttribute(tc_gemm<0,0>, cudaFuncAttributeMaxDynamicSharedMemorySize, SMEM_BYTES);
    cudaFuncSetAttribute(tc_gemm<1,0>, cudaFuncAttributeMaxDynamicSharedMemorySize, SMEM_BYTES);
    cudaFuncSetAttribute(tc_gemm<2,1>, cudaFuncAttributeMaxDynamicSharedMemorySize, SMEM_BYTES);

    // 0. transpose weights once into scratch (all GEMMs are NT)
    transpose_kernel<<<dim3(16, 16), dim3(32, 8)>>>(Wq, WqT, DD, DD);
    transpose_kernel<<<dim3(16, 16), dim3(32, 8)>>>(Wk, WkT, DD, DD);
    transpose_kernel<<<dim3(16, 16), dim3(32, 8)>>>(Wv, WvT, DD, DD);
    transpose_kernel<<<dim3(16, 16), dim3(32, 8)>>>(Wm, WmT, DD, DD);
    transpose_kernel<<<dim3(32, 32), dim3(32, 8)>>>(W1, W1T, 2 * DD, 2 * DD);
    transpose_kernel<<<dim3(16, 32), dim3(32, 8)>>>(W2, W2T, 2 * DD, DD);

    // 1. projections
    tc_gemm<0,0><<<dim3(4, 64, 1),  256, SMEM_BYTES>>>(x,   nullptr, WqT, q, DD, DD, DD, DD, 0, 0, 0, nullptr, nullptr);
    tc_gemm<0,0><<<dim3(4, 256, 1), 256, SMEM_BYTES>>>(src, nullptr, WkT, k, DD, DD, DD, DD, 0, 0, 0, nullptr, nullptr);
    // vT[b] = WvT @ src[b]^T
    tc_gemm<0,0><<<dim3(SSEQ / 128, DD / 128, NB), 256, SMEM_BYTES>>>(
        WvT, nullptr, src, vT, SSEQ, DD, DD, DD,
        0, (long long)SSEQ * DD, (long long)DD * SSEQ, nullptr, nullptr);

    // 2. squared row norms
    rownorm2_kernel<<<NB * LQ,   128>>>(q, q2);
    rownorm2_kernel<<<NB * SSEQ, 128>>>(k, k2);

    // 3. distances: sc = sqrt(max(q2 + k2 - 2 q.k, 0))
    tc_gemm<1,0><<<dim3(SSEQ / 128, LQ / 128, NB), 256, SMEM_BYTES>>>(
        q, nullptr, k, sc, SSEQ, DD, DD, DD,
        (long long)LQ * DD, (long long)SSEQ * DD, (long long)LQ * SSEQ, q2, k2);

    // 4. softmax over S (in place)
    softmax_rows_kernel<<<NB * LQ, 256>>>();

    // 5. message = attn @ v  (NT with vT)
    tc_gemm<0,0><<<dim3(4, LQ / 128, NB), 256, SMEM_BYTES>>>(
        sc, nullptr, vT, msg, DD, SSEQ, SSEQ, SSEQ,
        (long long)LQ * SSEQ, (long long)DD * SSEQ, (long long)LQ * DD, nullptr, nullptr);

    // 6. mw = message @ Wm ; mln = LN(mw)
    tc_gemm<0,0><<<dim3(4, 64, 1), 256, SMEM_BYTES>>>(msg, nullptr, WmT, mw, DD, DD, DD, DD, 0, 0, 0, nullptr, nullptr);
    layernorm_kernel<<<NB * LQ, 128>>>(mw, g1, b1, nullptr, mln);

    // 7. hid = relu([x, mln] @ W1)
    tc_gemm<2,1><<<dim3(8, 64, 1), 256, SMEM_BYTES>>>(x, mln, W1T, hid, 2 * DD, 2 * DD, DD, 2 * DD, 0, 0, 0, nullptr, nullptr);

    // 8. ffn = hid @ W2
    tc_gemm<0,0><<<dim3(4, 64, 1), 256, SMEM_BYTES>>>(hid, nullptr, W2T, ffn, DD, 2 * DD, 2 * DD, 2 * DD, 0, 0, 0, nullptr, nullptr);

    // 9. out = x + LN(ffn)
    layernorm_kernel<<<NB * LQ, 128>>>(ffn, g2, b2, x, out);
}

// round 7
// speedup vs baseline: 1.9483x; 1.9483x over previous
#include <cuda_runtime.h>
#include <cuda_fp16.h>
#include <cstdint>

// Problem dims (fixed)
#define NB   8
#define LQ   1024
#define SSEQ 4096
#define DD   512

// tcgen05 is an arch-specific ('a') feature: only emit it in device passes that
// target sm_103a/sm_100a-class specifics. The plain compute_103 pass gets a
// correct mma.sync fallback so ptxas never sees tcgen05 text.
#ifndef __CUDA_ARCH_SPECIFIC__
#define __CUDA_ARCH_SPECIFIC__ 0
#endif
#if defined(__CUDA_ARCH_FEAT_SM103_ALL) || defined(__CUDA_ARCH_FEAT_SM100_ALL) || (__CUDA_ARCH_SPECIFIC__ >= 1000)
#define HAS_TCGEN05 1
#else
#define HAS_TCGEN05 0
#endif

// ---------------- static device scratch (no allocations allowed) ----------------
static __device__ float g_q  [NB * LQ * DD];
static __device__ float g_k  [NB * SSEQ * DD];
static __device__ float g_vT [NB * DD * SSEQ];        // v transposed: [b][d][s]
static __device__ float g_q2 [NB * LQ];
static __device__ float g_k2 [NB * SSEQ];
static __device__ float g_s  [NB * LQ * SSEQ];        // scores -> attn in place
static __device__ float g_msg[NB * LQ * DD];
static __device__ float g_mw [NB * LQ * DD];
static __device__ float g_mln[NB * LQ * DD];
static __device__ float g_hid[NB * LQ * 2 * DD];
static __device__ float g_ffn[NB * LQ * DD];
static __device__ float g_wt [4 * DD * DD + 2 * DD * 2 * DD + 2 * DD * DD];

// ======================= PTX helpers =======================
__device__ __forceinline__ uint32_t smem_u32(const void* p) {
    uint32_t a;
    asm("{ .reg .u64 t; cvta.to.shared.u64 t, %1; cvt.u32.u64 %0, t; }" : "=r"(a) : "l"(p));
    return a;
}
__device__ __forceinline__ float to_tf32(float x) {
    float r;
    asm("cvt.rna.tf32.f32 %0, %1;" : "=f"(r) : "f"(x));
    return r;
}

#if HAS_TCGEN05
__device__ __forceinline__ uint32_t elect_one() {
    uint32_t pred;
    asm volatile("{\n\t.reg .pred p;\n\telect.sync _|p, 0xFFFFFFFF;\n\t"
                 "selp.b32 %0, 1, 0, p;\n\t}" : "=r"(pred));
    return pred;
}
#define MBAR_INIT(addr, cnt) \
    asm volatile("mbarrier.init.shared.b64 [%0], %1;" :: "r"(addr), "r"(cnt) : "memory")
#define MBAR_INVAL(addr) \
    asm volatile("mbarrier.inval.shared.b64 [%0];" :: "r"(addr) : "memory")
__device__ __forceinline__ void mbar_wait(uint32_t addr, uint32_t parity) {
    uint32_t done;
    asm volatile("{\n\t.reg .pred p;\n\t"
                 "mbarrier.try_wait.parity.acquire.cta.shared::cta.b64 p, [%1], %2;\n\t"
                 "selp.b32 %0, 1, 0, p;\n\t}" : "=r"(done) : "r"(addr), "r"(parity) : "memory");
    if (!done) {
        asm volatile("{\n\t.reg .pred P1;\n\t"
                     "W_%=:\n\t"
                     "mbarrier.try_wait.parity.acquire.cta.shared::cta.b64 P1, [%0], %1, 0x989680;\n\t"
                     "@P1 bra.uni D_%=;\n\t"
                     "bra.uni W_%=;\n\t"
                     "D_%=:\n\t}" :: "r"(addr), "r"(parity) : "memory");
    }
}
#define TC_ALLOC(smem_addr, n) \
    asm volatile("tcgen05.alloc.cta_group::1.sync.aligned.shared::cta.b32 [%0], %1;" \
                 :: "r"(smem_addr), "r"(n) : "memory")
#define TC_DEALLOC(tmem, n) \
    asm volatile("tcgen05.dealloc.cta_group::1.sync.aligned.b32 %0, %1;" :: "r"(tmem), "r"(n))
#define TC_RELINQ() \
    asm volatile("tcgen05.relinquish_alloc_permit.cta_group::1.sync.aligned;")
#define TC_COMMIT(mbar) \
    asm volatile("tcgen05.commit.cta_group::1.mbarrier::arrive::one.shared::cluster.b64 [%0];" \
                 :: "r"(mbar) : "memory")
#define TC_FENCE_AFTER() asm volatile("tcgen05.fence::after_thread_sync;" ::: "memory")
#define TC_WAIT_LD()     asm volatile("tcgen05.wait::ld.sync.aligned;" ::: "memory")
#define FENCE_ASYNC()    asm volatile("fence.proxy.async.shared::cta;" ::: "memory")

__device__ __forceinline__ void mma_tf32_ss(uint32_t d, uint64_t a, uint64_t b,
                                            uint32_t idesc, uint32_t en) {
    asm volatile("{\n\t.reg .pred p;\n\tsetp.ne.u32 p, %4, 0;\n\t"
                 "tcgen05.mma.cta_group::1.kind::tf32 [%0], %1, %2, %3, {%5,%5,%5,%5}, p;\n\t}"
                 :: "r"(d), "l"(a), "l"(b), "r"(idesc), "r"(en), "r"(0u) : "memory");
}
__device__ __forceinline__ void tmem_ld_x32(uint32_t* r, uint32_t addr) {
    asm volatile(
        "tcgen05.ld.sync.aligned.32x32b.x32.b32 "
        "{%0,%1,%2,%3,%4,%5,%6,%7,%8,%9,%10,%11,%12,%13,%14,%15,"
        "%16,%17,%18,%19,%20,%21,%22,%23,%24,%25,%26,%27,%28,%29,%30,%31}, [%32];"
        : "=r"(r[0]), "=r"(r[1]), "=r"(r[2]), "=r"(r[3]), "=r"(r[4]), "=r"(r[5]),
          "=r"(r[6]), "=r"(r[7]), "=r"(r[8]), "=r"(r[9]), "=r"(r[10]), "=r"(r[11]),
          "=r"(r[12]), "=r"(r[13]), "=r"(r[14]), "=r"(r[15]), "=r"(r[16]), "=r"(r[17]),
          "=r"(r[18]), "=r"(r[19]), "=r"(r[20]), "=r"(r[21]), "=r"(r[22]), "=r"(r[23]),
          "=r"(r[24]), "=r"(r[25]), "=r"(r[26]), "=r"(r[27]), "=r"(r[28]), "=r"(r[29]),
          "=r"(r[30]), "=r"(r[31])
        : "r"(addr));
}
// SW128 swizzle on byte offsets (Swizzle<3,4,3>)
__device__ __forceinline__ uint32_t sw128(uint32_t b) { return b ^ ((b >> 3) & 0x70); }
// SMEM descriptor: SW128, version 1 (Blackwell), LBO=1, SBO=64
static __device__ __forceinline__ uint64_t make_desc(uint32_t addr) {
    const uint64_t base = (uint64_t(2) << 61) | (uint64_t(1) << 46)
                        | (uint64_t(64) << 32) | (uint64_t(1) << 16);
    return base | ((uint64_t)(addr >> 4) & 0x3FFF);
}
// idesc: D=F32, A=B=TF32 K-major, M=128, N=128
#define IDESC_TF32 ((1u << 4) | (2u << 7) | (2u << 10) | ((128u / 8u) << 17) | ((128u / 16u) << 24))
#endif  // HAS_TCGEN05

// ======================================================================
// NT GEMM: C[M,N] = A[M,K] * Bt[N,K]^T, fp32 accumulate, 128x128 CTA tile.
// sm_103a pass: tcgen05 tf32 SS pipeline:
//   - 4-slot smem ring (4 x 32KB), one mbarrier per slot
//   - 2x-unrolled mainloop with two STATIC register sets (no dynamic
//     register-array indexing -> no local-memory spill), prefetch distance 1
//   - one elected thread issues 4 K=8 MMAs + commit per stage
// other passes: fp16 mma.sync fallback (correct, slower; never runs on GB300).
// EPI: 0 none, 1 dist sqrt(max(rn[r]+cn[c]-2acc,0)), 2 relu.
// DUAL: A logical K = 2*512, first half gA, second gA2 (both lda=512).
// ======================================================================
template<int EPI, int DUAL>
__global__ __launch_bounds__(256)
void tc_gemm(const float* __restrict__ gA, const float* __restrict__ gA2,
             const float* __restrict__ gB, float* __restrict__ gC,
             int N, int K, int lda, int ldb,
             long long sA, long long sB, long long sC,
             const float* __restrict__ rn, const float* __restrict__ cn)
{
    extern __shared__ __align__(1024) char dyn_smem[];

    const int tid = threadIdx.x;
    const int wid = tid >> 5, lane = tid & 31;

    const long long z = blockIdx.z;
    const float* Abase  = gA + z * sA + (long long)blockIdx.y * 128 * lda;
    const float* A2base = DUAL ? (gA2 + (long long)blockIdx.y * 128 * lda) : nullptr;
    const float* Bbase  = gB + z * sB + (long long)blockIdx.x * 128 * ldb;
    float* Cbase = gC + z * sC + (long long)blockIdx.y * 128 * N + blockIdx.x * 128;

#if HAS_TCGEN05
    // ------------------------- tcgen05 path -------------------------
    __shared__ uint32_t s_tmem[1];
    __shared__ __align__(8) uint64_t s_mbar[4];

    const uint32_t smem_base = smem_u32(dyn_smem);
    uint32_t mbar[4];
#pragma unroll
    for (int i = 0; i < 4; i++) mbar[i] = smem_u32(&s_mbar[i]);

    if (wid == 0) {
        TC_ALLOC(smem_u32(s_tmem), 128);
        TC_RELINQ();
    }
    if (tid == 0) {
#pragma unroll
        for (int i = 0; i < 4; i++) MBAR_INIT(mbar[i], 1);
    }
    __syncthreads();
    const uint32_t tmem = s_tmem[0];

    // loader geometry: tile = 128 rows x 32 floats (128B rows, SW128)
    const int r0 = tid >> 3, c0 = tid & 7;

    float4 pa0[4], pb0[4], pa1[4], pb1[4];   // two STATIC sets

    auto load_set = [&](int s, float4 (&pa)[4], float4 (&pb)[4]) {
        const int k0 = s * 32;
        const float* Ap = DUAL ? (k0 < 512 ? Abase + k0 : A2base + (k0 - 512)) : (Abase + k0);
        const float* Bp = Bbase + k0;
#pragma unroll
        for (int j = 0; j < 4; j++) {
            int row = r0 + j * 32;
            pa[j] = *(const float4*)(Ap + (long long)row * lda + c0 * 4);
            pb[j] = *(const float4*)(Bp + (long long)row * ldb + c0 * 4);
        }
    };
    auto store_set = [&](int slot, const float4 (&pa)[4], const float4 (&pb)[4]) {
        char* aB = dyn_smem + slot * 32768;
        char* bB = aB + 16384;
#pragma unroll
        for (int j = 0; j < 4; j++) {
            int row = r0 + j * 32;
            uint32_t off = sw128((uint32_t)(row * 128 + c0 * 16));
            float4 ta, tb;
            ta.x = to_tf32(pa[j].x); ta.y = to_tf32(pa[j].y);
            ta.z = to_tf32(pa[j].z); ta.w = to_tf32(pa[j].w);
            tb.x = to_tf32(pb[j].x); tb.y = to_tf32(pb[j].y);
            tb.z = to_tf32(pb[j].z); tb.w = to_tf32(pb[j].w);
            *(float4*)(aB + off) = ta;
            *(float4*)(bB + off) = tb;
        }
    };
    auto issue_mma = [&](int s) {
        if (wid == 0) {
            FENCE_ASYNC();
            if (elect_one()) {
                const int slot = s & 3;
                uint32_t aAddr = smem_base + slot * 32768;
                uint64_t ad = make_desc(aAddr);
                uint64_t bd = make_desc(aAddr + 16384);
#pragma unroll
                for (int st = 0; st < 4; st++)
                    mma_tf32_ss(tmem, ad + st * 2, bd + st * 2, IDESC_TF32,
                                (s > 0 || st > 0) ? 1u : 0u);
                TC_COMMIT(mbar[slot]);
            }
        }
    };

    const int nst = K / 32;                  // 16 / 32 / 128 -> always even
    load_set(0, pa0, pb0);
    for (int s = 0; s < nst; s += 2) {
        // ---- stage s (set 0) ----
        load_set(s + 1, pa1, pb1);                             // prefetch next
        if (s >= 4) mbar_wait(mbar[s & 3], ((s >> 2) - 1) & 1); // slot reuse guard
        store_set(s & 3, pa0, pb0);
        __syncthreads();
        issue_mma(s);
        // ---- stage s+1 (set 1) ----
        if (s + 2 < nst) load_set(s + 2, pa0, pb0);            // prefetch next
        if (s + 1 >= 4) mbar_wait(mbar[(s + 1) & 3], (((s + 1) >> 2) - 1) & 1);
        store_set((s + 1) & 3, pa1, pb1);
        __syncthreads();
        issue_mma(s + 1);
    }
    {   // drain: last commit tracks ALL prior MMAs of this CTA
        const int L = nst - 1;
        mbar_wait(mbar[L & 3], (L >> 2) & 1);
    }
    TC_FENCE_AFTER();

    // epilogue: TMEM -> regs -> smem (coalesce) -> gmem
    float* stg = (float*)dyn_smem;                      // [128][33] staging
    const int Mtot = gridDim.y * 128;
    float rv = 0.0f, cnv = 0.0f;
    if (EPI == 1 && wid < 4)
        rv = rn[z * Mtot + (long long)blockIdx.y * 128 + wid * 32 + lane];

#pragma unroll
    for (int ch = 0; ch < 4; ch++) {
        if (wid < 4) {
            uint32_t r[32];
            tmem_ld_x32(r, tmem + ch * 32);
            TC_WAIT_LD();
            if (EPI == 1) cnv = cn[z * N + (long long)blockIdx.x * 128 + ch * 32 + lane];
            int row = wid * 32 + lane;
#pragma unroll
            for (int c = 0; c < 32; c++) {
                float v = __uint_as_float(r[c]);
                if (EPI == 1) {
                    float cc = __shfl_sync(0xffffffffu, cnv, c);
                    v = sqrtf(fmaxf(rv + cc - 2.0f * v, 0.0f));
                } else if (EPI == 2) {
                    v = fmaxf(v, 0.0f);
                }
                stg[row * 33 + c] = v;
            }
        }
        __syncthreads();
#pragma unroll
        for (int it = 0; it < 16; it++) {
            int row = wid + it * 8;
            Cbase[(long long)row * N + ch * 32 + lane] = stg[row * 33 + lane];
        }
        __syncthreads();
    }

    if (tid == 0) {
#pragma unroll
        for (int i = 0; i < 4; i++) MBAR_INVAL(mbar[i]);
    }
    __syncthreads();
    if (wid == 0) TC_DEALLOC(tmem, 128);

#else
    // ------------------------- fp16 mma.sync fallback -------------------------
    __half* As = (__half*)dyn_smem;                 // [2][128*40]
    __half* Bs = (__half*)dyn_smem + 2 * 128 * 40;  // [2][128*40]

    const int gid = lane >> 2, ctig = lane & 3;
    const int wm = (wid & 1) * 64;
    const int wn = (wid >> 1) * 32;
    const int aRow = tid >> 1;
    const int aOff = (tid & 1) * 16;

    float4 pa[4], pb[4];
    auto loadA = [&](int k0) {
        const float* Ap = DUAL ? (k0 < 512 ? Abase + k0 : A2base + (k0 - 512)) : (Abase + k0);
        const float* r = Ap + (long long)aRow * lda + aOff;
#pragma unroll
        for (int j = 0; j < 4; j++) pa[j] = *(const float4*)(r + 4 * j);
    };
    auto loadB = [&](int k0) {
        const float* r = Bbase + (long long)aRow * ldb + k0 + aOff;
#pragma unroll
        for (int j = 0; j < 4; j++) pb[j] = *(const float4*)(r + 4 * j);
    };
    auto storeAB = [&](int buf) {
        __half* Ab = As + buf * 128 * 40;
        __half* Bb = Bs + buf * 128 * 40;
#pragma unroll
        for (int j = 0; j < 4; j++) {
            *(__half2*)&Ab[aRow * 40 + aOff + 4 * j]     = __floats2half2_rn(pa[j].x, pa[j].y);
            *(__half2*)&Ab[aRow * 40 + aOff + 4 * j + 2] = __floats2half2_rn(pa[j].z, pa[j].w);
            *(__half2*)&Bb[aRow * 40 + aOff + 4 * j]     = __floats2half2_rn(pb[j].x, pb[j].y);
            *(__half2*)&Bb[aRow * 40 + aOff + 4 * j + 2] = __floats2half2_rn(pb[j].z, pb[j].w);
        }
    };

    float c[4][4][4];
#pragma unroll
    for (int mi = 0; mi < 4; mi++)
#pragma unroll
        for (int ni = 0; ni < 4; ni++)
#pragma unroll
            for (int r = 0; r < 4; r++) c[mi][ni][r] = 0.0f;

    loadA(0); loadB(0);
    storeAB(0);
    __syncthreads();

    const int nst = K / 32;
    for (int s = 0; s < nst; s++) {
        const int buf = s & 1;
        const __half* Ab = As + buf * 128 * 40;
        const __half* Bb = Bs + buf * 128 * 40;
        if (s + 1 < nst) { loadA((s + 1) * 32); loadB((s + 1) * 32); }
#pragma unroll
        for (int ks = 0; ks < 2; ks++) {
            const int kb = ks * 16;
            unsigned a[4][4], b[4][2];
#pragma unroll
            for (int mi = 0; mi < 4; mi++) {
                int r0 = wm + mi * 16 + gid;
                a[mi][0] = *(const unsigned*)&Ab[r0 * 40 + kb + 2 * ctig];
                a[mi][1] = *(const unsigned*)&Ab[(r0 + 8) * 40 + kb + 2 * ctig];
                a[mi][2] = *(const unsigned*)&Ab[r0 * 40 + kb + 8 + 2 * ctig];
                a[mi][3] = *(const unsigned*)&Ab[(r0 + 8) * 40 + kb + 8 + 2 * ctig];
            }
#pragma unroll
            for (int ni = 0; ni < 4; ni++) {
                int cc = wn + ni * 8 + gid;
                b[ni][0] = *(const unsigned*)&Bb[cc * 40 + kb + 2 * ctig];
                b[ni][1] = *(const unsigned*)&Bb[cc * 40 + kb + 8 + 2 * ctig];
            }
#pragma unroll
            for (int mi = 0; mi < 4; mi++)
#pragma unroll
                for (int ni = 0; ni < 4; ni++) {
                    asm volatile(
                        "mma.sync.aligned.m16n8k16.row.col.f32.f16.f16.f32 "
                        "{%0,%1,%2,%3}, {%4,%5,%6,%7}, {%8,%9}, {%0,%1,%2,%3};\n"
                        : "+f"(c[mi][ni][0]), "+f"(c[mi][ni][1]),
                          "+f"(c[mi][ni][2]), "+f"(c[mi][ni][3])
                        : "r"(a[mi][0]), "r"(a[mi][1]), "r"(a[mi][2]), "r"(a[mi][3]),
                          "r"(b[ni][0]), "r"(b[ni][1]));
                }
        }
        if (s + 1 < nst) storeAB(buf ^ 1);
        __syncthreads();
    }

    const int Mtot = gridDim.y * 128;
    const float* rnp = (EPI == 1) ? (rn + z * Mtot + (long long)blockIdx.y * 128) : nullptr;
    const float* cnp = (EPI == 1) ? (cn + z * N + blockIdx.x * 128) : nullptr;
#pragma unroll
    for (int mi = 0; mi < 4; mi++) {
#pragma unroll
        for (int half = 0; half < 2; half++) {
            int r = wm + mi * 16 + gid + half * 8;
            float rvv = (EPI == 1) ? rnp[r] : 0.0f;
#pragma unroll
            for (int ni = 0; ni < 4; ni++) {
                int cc = wn + ni * 8 + 2 * ctig;
                float v0 = c[mi][ni][half * 2 + 0];
                float v1 = c[mi][ni][half * 2 + 1];
                if (EPI == 1) {
                    v0 = sqrtf(fmaxf(rvv + cnp[cc]     - 2.0f * v0, 0.0f));
                    v1 = sqrtf(fmaxf(rvv + cnp[cc + 1] - 2.0f * v1, 0.0f));
                } else if (EPI == 2) {
                    v0 = fmaxf(v0, 0.0f);
                    v1 = fmaxf(v1, 0.0f);
                }
                *(float2*)(Cbase + (long long)r * N + cc) = make_float2(v0, v1);
            }
        }
    }
#endif
}

// ---------------- reductions ----------------
__device__ __forceinline__ float warpReduceSum(float v) {
    v += __shfl_xor_sync(0xffffffffu, v, 16);
    v += __shfl_xor_sync(0xffffffffu, v, 8);
    v += __shfl_xor_sync(0xffffffffu, v, 4);
    v += __shfl_xor_sync(0xffffffffu, v, 2);
    v += __shfl_xor_sync(0xffffffffu, v, 1);
    return v;
}
__device__ __forceinline__ float warpReduceMax(float v) {
    v = fmaxf(v, __shfl_xor_sync(0xffffffffu, v, 16));
    v = fmaxf(v, __shfl_xor_sync(0xffffffffu, v, 8));
    v = fmaxf(v, __shfl_xor_sync(0xffffffffu, v, 4));
    v = fmaxf(v, __shfl_xor_sync(0xffffffffu, v, 2));
    v = fmaxf(v, __shfl_xor_sync(0xffffffffu, v, 1));
    return v;
}
__device__ __forceinline__ float blockAllReduceSum(float v, float* sh) {
    int lane = threadIdx.x & 31, wid = threadIdx.x >> 5;
    v = warpReduceSum(v);
    if (lane == 0) sh[wid] = v;
    __syncthreads();
    int nw = blockDim.x >> 5;
    float t = (lane < nw) ? sh[lane] : 0.0f;
    t = warpReduceSum(t);
    __syncthreads();
    return t;
}
__device__ __forceinline__ float blockAllReduceMax(float v, float* sh) {
    int lane = threadIdx.x & 31, wid = threadIdx.x >> 5;
    v = warpReduceMax(v);
    if (lane == 0) sh[wid] = v;
    __syncthreads();
    int nw = blockDim.x >> 5;
    float t = (lane < nw) ? sh[lane] : -3.0e38f;
    t = warpReduceMax(t);
    __syncthreads();
    return t;
}

// ---------------- fp32 transpose (R,C multiples of 32): out[C,R] = in[R,C]^T ----
__global__ __launch_bounds__(256)
void transpose_kernel(const float* __restrict__ in, float* __restrict__ out,
                      int R, int C)
{
    __shared__ float t[32][33];
    int bx = blockIdx.x * 32, by = blockIdx.y * 32;
    int x = bx + threadIdx.x;
#pragma unroll
    for (int j = 0; j < 32; j += 8)
        t[threadIdx.y + j][threadIdx.x] = in[(long long)(by + threadIdx.y + j) * C + x];
    __syncthreads();
    int x2 = by + threadIdx.x;
#pragma unroll
    for (int j = 0; j < 32; j += 8)
        out[(long long)(bx + threadIdx.y + j) * R + x2] = t[threadIdx.x][threadIdx.y + j];
}

// ---------------- row squared-norm ----------------
__global__ __launch_bounds__(128)
void rownorm2_kernel(const float* __restrict__ X, float* __restrict__ out)
{
    __shared__ float sh[32];
    long long row = blockIdx.x;
    const float* x = X + row * DD;
    float4 v = *(const float4*)(x + threadIdx.x * 4);
    float s = v.x * v.x + v.y * v.y + v.z * v.z + v.w * v.w;
    s = blockAllReduceSum(s, sh);
    if (threadIdx.x == 0) out[row] = s;
}

// ---------------- softmax over S=4096, in place on g_s ----------------
__global__ __launch_bounds__(256)
void softmax_rows_kernel()
{
    __shared__ float sh[32];
    long long row = blockIdx.x;
    float* p = g_s + row * SSEQ;
    int t = threadIdx.x;

    float4 f[4];
    float mx = -3.0e38f;
#pragma unroll
    for (int i = 0; i < 4; i++) {
        f[i] = *(const float4*)(p + i * 1024 + t * 4);
        mx = fmaxf(mx, fmaxf(fmaxf(f[i].x, f[i].y), fmaxf(f[i].z, f[i].w)));
    }
    mx = blockAllReduceMax(mx, sh);

    float sum = 0.0f;
#pragma unroll
    for (int i = 0; i < 4; i++) {
        f[i].x = __expf(f[i].x - mx);
        f[i].y = __expf(f[i].y - mx);
        f[i].z = __expf(f[i].z - mx);
        f[i].w = __expf(f[i].w - mx);
        sum += f[i].x + f[i].y + f[i].z + f[i].w;
    }
    sum = blockAllReduceSum(sum, sh);
    float r = 1.0f / sum;
#pragma unroll
    for (int i = 0; i < 4; i++) {
        f[i].x *= r; f[i].y *= r; f[i].z *= r; f[i].w *= r;
        *(float4*)(p + i * 1024 + t * 4) = f[i];
    }
}

// ---------------- LayerNorm over D=512 (+ optional residual) ----------------
__global__ __launch_bounds__(128)
void layernorm_kernel(const float* __restrict__ X, const float* __restrict__ G,
                      const float* __restrict__ Bv, const float* __restrict__ R,
                      float* __restrict__ O)
{
    __shared__ float sh[32];
    long long row = blockIdx.x;
    int c = threadIdx.x * 4;
    float4 v = *(const float4*)(X + row * DD + c);

    float s = v.x + v.y + v.z + v.w;
    s = blockAllReduceSum(s, sh);
    float mu = s * (1.0f / DD);

    float d0 = v.x - mu, d1 = v.y - mu, d2 = v.z - mu, d3 = v.w - mu;
    float s2 = d0 * d0 + d1 * d1 + d2 * d2 + d3 * d3;
    s2 = blockAllReduceSum(s2, sh);
    float inv = rsqrtf(s2 * (1.0f / DD) + 1e-5f);

    float4 gg = *(const float4*)(G + c);
    float4 bb = *(const float4*)(Bv + c);
    float4 o;
    o.x = d0 * inv * gg.x + bb.x;
    o.y = d1 * inv * gg.y + bb.y;
    o.z = d2 * inv * gg.z + bb.z;
    o.w = d3 * inv * gg.w + bb.w;
    if (R) {
        float4 rr = *(const float4*)(R + row * DD + c);
        o.x += rr.x; o.y += rr.y; o.z += rr.z; o.w += rr.w;
    }
    *(float4*)(O + row * DD + c) = o;
}

// ======================================================================
#define SMEM_BYTES 131072

extern "C" void kernel_launch(void* const* d_in, const int* in_sizes, int n_in,
                              void* d_out, int out_size)
{
    (void)in_sizes; (void)n_in; (void)out_size;
    const float* x   = (const float*)d_in[0];
    const float* src = (const float*)d_in[1];
    const float* Wq  = (const float*)d_in[2];
    const float* Wk  = (const float*)d_in[3];
    const float* Wv  = (const float*)d_in[4];
    const float* Wm  = (const float*)d_in[5];
    const float* W1  = (const float*)d_in[6];
    const float* W2  = (const float*)d_in[7];
    const float* g1  = (const float*)d_in[8];
    const float* b1  = (const float*)d_in[9];
    const float* g2  = (const float*)d_in[10];
    const float* b2  = (const float*)d_in[11];
    float* out = (float*)d_out;

    float *q, *k, *vT, *q2, *k2, *sc, *msg, *mw, *mln, *hid, *ffn, *wt;
    cudaGetSymbolAddress((void**)&q,   g_q);
    cudaGetSymbolAddress((void**)&k,   g_k);
    cudaGetSymbolAddress((void**)&vT,  g_vT);
    cudaGetSymbolAddress((void**)&q2,  g_q2);
    cudaGetSymbolAddress((void**)&k2,  g_k2);
    cudaGetSymbolAddress((void**)&sc,  g_s);
    cudaGetSymbolAddress((void**)&msg, g_msg);
    cudaGetSymbolAddress((void**)&mw,  g_mw);
    cudaGetSymbolAddress((void**)&mln, g_mln);
    cudaGetSymbolAddress((void**)&hid, g_hid);
    cudaGetSymbolAddress((void**)&ffn, g_ffn);
    cudaGetSymbolAddress((void**)&wt,  g_wt);

    float* WqT = wt;
    float* WkT = wt + DD * DD;
    float* WvT = wt + 2 * DD * DD;
    float* WmT = wt + 3 * DD * DD;
    float* W1T = wt + 4 * DD * DD;
    float* W2T = wt + 8 * DD * DD;

    cudaFuncSetAttribute(tc_gemm<0,0>, cudaFuncAttributeMaxDynamicSharedMemorySize, SMEM_BYTES);
    cudaFuncSetAttribute(tc_gemm<1,0>, cudaFuncAttributeMaxDynamicSharedMemorySize, SMEM_BYTES);
    cudaFuncSetAttribute(tc_gemm<2,1>, cudaFuncAttributeMaxDynamicSharedMemorySize, SMEM_BYTES);

    // 0. transpose weights once into scratch (all GEMMs are NT)
    transpose_kernel<<<dim3(16, 16), dim3(32, 8)>>>(Wq, WqT, DD, DD);
    transpose_kernel<<<dim3(16, 16), dim3(32, 8)>>>(Wk, WkT, DD, DD);
    transpose_kernel<<<dim3(16, 16), dim3(32, 8)>>>(Wv, WvT, DD, DD);
    transpose_kernel<<<dim3(16, 16), dim3(32, 8)>>>(Wm, WmT, DD, DD);
    transpose_kernel<<<dim3(32, 32), dim3(32, 8)>>>(W1, W1T, 2 * DD, 2 * DD);
    transpose_kernel<<<dim3(16, 32), dim3(32, 8)>>>(W2, W2T, 2 * DD, DD);

    // 1. projections
    tc_gemm<0,0><<<dim3(4, 64, 1),  256, SMEM_BYTES>>>(x,   nullptr, WqT, q, DD, DD, DD, DD, 0, 0, 0, nullptr, nullptr);
    tc_gemm<0,0><<<dim3(4, 256, 1), 256, SMEM_BYTES>>>(src, nullptr, WkT, k, DD, DD, DD, DD, 0, 0, 0, nullptr, nullptr);
    // vT[b] = WvT @ src[b]^T
    tc_gemm<0,0><<<dim3(SSEQ / 128, DD / 128, NB), 256, SMEM_BYTES>>>(
        WvT, nullptr, src, vT, SSEQ, DD, DD, DD,
        0, (long long)SSEQ * DD, (long long)DD * SSEQ, nullptr, nullptr);

    // 2. squared row norms
    rownorm2_kernel<<<NB * LQ,   128>>>(q, q2);
    rownorm2_kernel<<<NB * SSEQ, 128>>>(k, k2);

    // 3. distances: sc = sqrt(max(q2 + k2 - 2 q.k, 0))
    tc_gemm<1,0><<<dim3(SSEQ / 128, LQ / 128, NB), 256, SMEM_BYTES>>>(
        q, nullptr, k, sc, SSEQ, DD, DD, DD,
        (long long)LQ * DD, (long long)SSEQ * DD, (long long)LQ * SSEQ, q2, k2);

    // 4. softmax over S (in place)
    softmax_rows_kernel<<<NB * LQ, 256>>>();

    // 5. message = attn @ v  (NT with vT)
    tc_gemm<0,0><<<dim3(4, LQ / 128, NB), 256, SMEM_BYTES>>>(
        sc, nullptr, vT, msg, DD, SSEQ, SSEQ, SSEQ,
        (long long)LQ * SSEQ, (long long)DD * SSEQ, (long long)LQ * DD, nullptr, nullptr);

    // 6. mw = message @ Wm ; mln = LN(mw)
    tc_gemm<0,0><<<dim3(4, 64, 1), 256, SMEM_BYTES>>>(msg, nullptr, WmT, mw, DD, DD, DD, DD, 0, 0, 0, nullptr, nullptr);
    layernorm_kernel<<<NB * LQ, 128>>>(mw, g1, b1, nullptr, mln);

    // 7. hid = relu([x, mln] @ W1)
    tc_gemm<2,1><<<dim3(8, 64, 1), 256, SMEM_BYTES>>>(x, mln, W1T, hid, 2 * DD, 2 * DD, DD, 2 * DD, 0, 0, 0, nullptr, nullptr);

    // 8. ffn = hid @ W2
    tc_gemm<0,0><<<dim3(4, 64, 1), 256, SMEM_BYTES>>>(hid, nullptr, W2T, ffn, DD, 2 * DD, 2 * DD, 2 * DD, 0, 0, 0, nullptr, nullptr);

    // 9. out = x + LN(ffn)
    layernorm_kernel<<<NB * LQ, 128>>>(ffn, g2, b2, x, out);
}

// round 8
// speedup vs baseline: 2.7439x; 1.4084x over previous
#include <cuda_runtime.h>
#include <cuda_fp16.h>
#include <cstdint>

// Problem dims (fixed)
#define NB   8
#define LQ   1024
#define SSEQ 4096
#define DD   512

#ifndef __CUDA_ARCH_SPECIFIC__
#define __CUDA_ARCH_SPECIFIC__ 0
#endif
#if defined(__CUDA_ARCH_FEAT_SM103_ALL) || defined(__CUDA_ARCH_FEAT_SM100_ALL) || (__CUDA_ARCH_SPECIFIC__ >= 1000)
#define HAS_TCGEN05 1
#else
#define HAS_TCGEN05 0
#endif

// ---------------- static device scratch (no allocations allowed) ----------------
static __device__ float g_q  [NB * LQ * DD];
static __device__ float g_k  [NB * SSEQ * DD];
static __device__ float g_vT [NB * DD * SSEQ];
static __device__ float g_q2 [NB * LQ];
static __device__ float g_k2 [NB * SSEQ];
static __device__ float g_s  [NB * LQ * SSEQ];
static __device__ float g_msg[NB * LQ * DD];
static __device__ float g_mw [NB * LQ * DD];
static __device__ float g_mln[NB * LQ * DD];
static __device__ float g_hid[NB * LQ * 2 * DD];
static __device__ float g_ffn[NB * LQ * DD];
static __device__ float g_wt [4 * DD * DD + 2 * DD * 2 * DD + 2 * DD * DD];
static __device__ float g_xr [NB * LQ * DD];          // tf32-rounded x
static __device__ float g_srcr[NB * SSEQ * DD];       // tf32-rounded source

// ======================= PTX helpers =======================
__device__ __forceinline__ uint32_t smem_u32(const void* p) {
    uint32_t a;
    asm("{ .reg .u64 t; cvta.to.shared.u64 t, %1; cvt.u32.u64 %0, t; }" : "=r"(a) : "l"(p));
    return a;
}
__device__ __forceinline__ float to_tf32(float x) {
    float r;
    asm("cvt.rna.tf32.f32 %0, %1;" : "=f"(r) : "f"(x));
    return r;
}

#if HAS_TCGEN05
__device__ __forceinline__ uint32_t elect_one() {
    uint32_t pred;
    asm volatile("{\n\t.reg .pred p;\n\telect.sync _|p, 0xFFFFFFFF;\n\t"
                 "selp.b32 %0, 1, 0, p;\n\t}" : "=r"(pred));
    return pred;
}
#define MBAR_INIT(addr, cnt) \
    asm volatile("mbarrier.init.shared.b64 [%0], %1;" :: "r"(addr), "r"(cnt) : "memory")
#define MBAR_INVAL(addr) \
    asm volatile("mbarrier.inval.shared.b64 [%0];" :: "r"(addr) : "memory")
__device__ __forceinline__ void mbar_wait(uint32_t addr, uint32_t parity) {
    uint32_t done;
    asm volatile("{\n\t.reg .pred p;\n\t"
                 "mbarrier.try_wait.parity.acquire.cta.shared::cta.b64 p, [%1], %2;\n\t"
                 "selp.b32 %0, 1, 0, p;\n\t}" : "=r"(done) : "r"(addr), "r"(parity) : "memory");
    if (!done) {
        asm volatile("{\n\t.reg .pred P1;\n\t"
                     "W_%=:\n\t"
                     "mbarrier.try_wait.parity.acquire.cta.shared::cta.b64 P1, [%0], %1, 0x989680;\n\t"
                     "@P1 bra.uni D_%=;\n\t"
                     "bra.uni W_%=;\n\t"
                     "D_%=:\n\t}" :: "r"(addr), "r"(parity) : "memory");
    }
}
#define TC_ALLOC(smem_addr, n) \
    asm volatile("tcgen05.alloc.cta_group::1.sync.aligned.shared::cta.b32 [%0], %1;" \
                 :: "r"(smem_addr), "r"(n) : "memory")
#define TC_DEALLOC(tmem, n) \
    asm volatile("tcgen05.dealloc.cta_group::1.sync.aligned.b32 %0, %1;" :: "r"(tmem), "r"(n))
#define TC_RELINQ() \
    asm volatile("tcgen05.relinquish_alloc_permit.cta_group::1.sync.aligned;")
#define TC_COMMIT(mbar) \
    asm volatile("tcgen05.commit.cta_group::1.mbarrier::arrive::one.shared::cluster.b64 [%0];" \
                 :: "r"(mbar) : "memory")
#define TC_FENCE_AFTER() asm volatile("tcgen05.fence::after_thread_sync;" ::: "memory")
#define TC_WAIT_LD()     asm volatile("tcgen05.wait::ld.sync.aligned;" ::: "memory")
#define FENCE_ASYNC()    asm volatile("fence.proxy.async.shared::cta;" ::: "memory")

__device__ __forceinline__ void mma_tf32_ss(uint32_t d, uint64_t a, uint64_t b,
                                            uint32_t idesc, uint32_t en) {
    asm volatile("{\n\t.reg .pred p;\n\tsetp.ne.u32 p, %4, 0;\n\t"
                 "tcgen05.mma.cta_group::1.kind::tf32 [%0], %1, %2, %3, {%5,%5,%5,%5}, p;\n\t}"
                 :: "r"(d), "l"(a), "l"(b), "r"(idesc), "r"(en), "r"(0u) : "memory");
}
__device__ __forceinline__ void tmem_ld_x32(uint32_t* r, uint32_t addr) {
    asm volatile(
        "tcgen05.ld.sync.aligned.32x32b.x32.b32 "
        "{%0,%1,%2,%3,%4,%5,%6,%7,%8,%9,%10,%11,%12,%13,%14,%15,"
        "%16,%17,%18,%19,%20,%21,%22,%23,%24,%25,%26,%27,%28,%29,%30,%31}, [%32];"
        : "=r"(r[0]), "=r"(r[1]), "=r"(r[2]), "=r"(r[3]), "=r"(r[4]), "=r"(r[5]),
          "=r"(r[6]), "=r"(r[7]), "=r"(r[8]), "=r"(r[9]), "=r"(r[10]), "=r"(r[11]),
          "=r"(r[12]), "=r"(r[13]), "=r"(r[14]), "=r"(r[15]), "=r"(r[16]), "=r"(r[17]),
          "=r"(r[18]), "=r"(r[19]), "=r"(r[20]), "=r"(r[21]), "=r"(r[22]), "=r"(r[23]),
          "=r"(r[24]), "=r"(r[25]), "=r"(r[26]), "=r"(r[27]), "=r"(r[28]), "=r"(r[29]),
          "=r"(r[30]), "=r"(r[31])
        : "r"(addr));
}
__device__ __forceinline__ uint32_t sw128(uint32_t b) { return b ^ ((b >> 3) & 0x70); }
static __device__ __forceinline__ uint64_t make_desc(uint32_t addr) {
    const uint64_t base = (uint64_t(2) << 61) | (uint64_t(1) << 46)
                        | (uint64_t(64) << 32) | (uint64_t(1) << 16);
    return base | ((uint64_t)(addr >> 4) & 0x3FFF);
}
#define IDESC_TF32 ((1u << 4) | (2u << 7) | (2u << 10) | ((128u / 8u) << 17) | ((128u / 16u) << 24))
#endif  // HAS_TCGEN05

// ======================================================================
// NT GEMM: C[M,N] = A[M,K] * Bt[N,K]^T, fp32 accumulate, 128x128 CTA tile.
// tcgen05 path: 3-slot smem ring (96KB -> 2 CTAs/SM), per-slot mbarriers,
// pure LDG->STS loader (operands are PRE-ROUNDED to tf32 by producers),
// prefetch distance 1 with two static register sets.
// EPI: 0 none, 1 dist, 2 relu.  ROUND: tf32-round C at store.
// DUAL: A logical K = 2*512, first half gA, second gA2 (both lda=512).
// ======================================================================
template<int EPI, int DUAL, int ROUND>
__global__ __launch_bounds__(256)
void tc_gemm(const float* __restrict__ gA, const float* __restrict__ gA2,
             const float* __restrict__ gB, float* __restrict__ gC,
             int N, int K, int lda, int ldb,
             long long sA, long long sB, long long sC,
             const float* __restrict__ rn, const float* __restrict__ cn)
{
    extern __shared__ __align__(1024) char dyn_smem[];

    const int tid = threadIdx.x;
    const int wid = tid >> 5, lane = tid & 31;

    const long long z = blockIdx.z;
    const float* Abase  = gA + z * sA + (long long)blockIdx.y * 128 * lda;
    const float* A2base = DUAL ? (gA2 + (long long)blockIdx.y * 128 * lda) : nullptr;
    const float* Bbase  = gB + z * sB + (long long)blockIdx.x * 128 * ldb;
    float* Cbase = gC + z * sC + (long long)blockIdx.y * 128 * N + blockIdx.x * 128;

#if HAS_TCGEN05
    __shared__ uint32_t s_tmem[1];
    __shared__ __align__(8) uint64_t s_mbar[3];

    const uint32_t smem_base = smem_u32(dyn_smem);
    const uint32_t mbar_base = smem_u32(&s_mbar[0]);

    if (wid == 0) {
        TC_ALLOC(smem_u32(s_tmem), 128);
        TC_RELINQ();
    }
    if (tid == 0) {
#pragma unroll
        for (int i = 0; i < 3; i++) MBAR_INIT(mbar_base + i * 8, 1);
    }
    __syncthreads();
    const uint32_t tmem = s_tmem[0];

    // loader geometry: tile = 128 rows x 32 floats (128B rows, SW128)
    const int r0 = tid >> 3, c0 = tid & 7;

    uint4 pa0[4], pb0[4], pa1[4], pb1[4];   // two STATIC sets, raw bit copies

    auto load_set = [&](int s, uint4 (&pa)[4], uint4 (&pb)[4]) {
        const int k0 = s * 32;
        const float* Ap = DUAL ? (k0 < 512 ? Abase + k0 : A2base + (k0 - 512)) : (Abase + k0);
        const float* Bp = Bbase + k0;
#pragma unroll
        for (int j = 0; j < 4; j++) {
            int row = r0 + j * 32;
            pa[j] = *(const uint4*)(Ap + (long long)row * lda + c0 * 4);
            pb[j] = *(const uint4*)(Bp + (long long)row * ldb + c0 * 4);
        }
    };
    auto store_set = [&](int slot, const uint4 (&pa)[4], const uint4 (&pb)[4]) {
        char* aB = dyn_smem + slot * 32768;
        char* bB = aB + 16384;
#pragma unroll
        for (int j = 0; j < 4; j++) {
            int row = r0 + j * 32;
            uint32_t off = sw128((uint32_t)(row * 128 + c0 * 16));
            *(uint4*)(aB + off) = pa[j];
            *(uint4*)(bB + off) = pb[j];
        }
    };
    auto issue_mma = [&](int s, int slot) {
        if (wid == 0) {
            FENCE_ASYNC();
            if (elect_one()) {
                uint32_t aAddr = smem_base + slot * 32768;
                uint64_t ad = make_desc(aAddr);
                uint64_t bd = make_desc(aAddr + 16384);
#pragma unroll
                for (int st = 0; st < 4; st++)
                    mma_tf32_ss(tmem, ad + st * 2, bd + st * 2, IDESC_TF32,
                                (s > 0 || st > 0) ? 1u : 0u);
                TC_COMMIT(mbar_base + slot * 8);
            }
        }
    };

    const int nst = K / 32;                  // 16 / 32 / 128 -> always even
    load_set(0, pa0, pb0);
    for (int s = 0; s < nst; s += 2) {
        {   // ---- stage s (set 0) ----
            const int slot = s % 3, rnd = s / 3;
            load_set(s + 1, pa1, pb1);
            if (rnd >= 1) mbar_wait(mbar_base + slot * 8, (rnd - 1) & 1);
            store_set(slot, pa0, pb0);
            __syncthreads();
            issue_mma(s, slot);
        }
        {   // ---- stage s+1 (set 1) ----
            const int s1 = s + 1;
            const int slot = s1 % 3, rnd = s1 / 3;
            if (s + 2 < nst) load_set(s + 2, pa0, pb0);
            if (rnd >= 1) mbar_wait(mbar_base + slot * 8, (rnd - 1) & 1);
            store_set(slot, pa1, pb1);
            __syncthreads();
            issue_mma(s1, slot);
        }
    }
    {   // drain: last commit tracks ALL prior MMAs of this CTA
        const int L = nst - 1;
        mbar_wait(mbar_base + (L % 3) * 8, (L / 3) & 1);
    }
    TC_FENCE_AFTER();

    // epilogue: TMEM -> regs -> smem (coalesce) -> gmem
    float* stg = (float*)dyn_smem;                      // [128][33] staging
    const int Mtot = gridDim.y * 128;
    float rv = 0.0f, cnv = 0.0f;
    if (EPI == 1 && wid < 4)
        rv = rn[z * Mtot + (long long)blockIdx.y * 128 + wid * 32 + lane];

#pragma unroll
    for (int ch = 0; ch < 4; ch++) {
        if (wid < 4) {
            uint32_t r[32];
            tmem_ld_x32(r, tmem + ch * 32);
            TC_WAIT_LD();
            if (EPI == 1) cnv = cn[z * N + (long long)blockIdx.x * 128 + ch * 32 + lane];
            int row = wid * 32 + lane;
#pragma unroll
            for (int c = 0; c < 32; c++) {
                float v = __uint_as_float(r[c]);
                if (EPI == 1) {
                    float cc = __shfl_sync(0xffffffffu, cnv, c);
                    v = sqrtf(fmaxf(rv + cc - 2.0f * v, 0.0f));
                } else if (EPI == 2) {
                    v = fmaxf(v, 0.0f);
                }
                if (ROUND) v = to_tf32(v);
                stg[row * 33 + c] = v;
            }
        }
        __syncthreads();
#pragma unroll
        for (int it = 0; it < 16; it++) {
            int row = wid + it * 8;
            Cbase[(long long)row * N + ch * 32 + lane] = stg[row * 33 + lane];
        }
        __syncthreads();
    }

    if (tid == 0) {
#pragma unroll
        for (int i = 0; i < 3; i++) MBAR_INVAL(mbar_base + i * 8);
    }
    __syncthreads();
    if (wid == 0) TC_DEALLOC(tmem, 128);

#else
    // ------------------------- fp16 mma.sync fallback (never runs on GB300) ----
    __half* As = (__half*)dyn_smem;
    __half* Bs = (__half*)dyn_smem + 2 * 128 * 40;

    const int gid = lane >> 2, ctig = lane & 3;
    const int wm = (wid & 1) * 64;
    const int wn = (wid >> 1) * 32;
    const int aRow = tid >> 1;
    const int aOff = (tid & 1) * 16;

    float4 pa[4], pb[4];
    auto loadA = [&](int k0) {
        const float* Ap = DUAL ? (k0 < 512 ? Abase + k0 : A2base + (k0 - 512)) : (Abase + k0);
        const float* r = Ap + (long long)aRow * lda + aOff;
#pragma unroll
        for (int j = 0; j < 4; j++) pa[j] = *(const float4*)(r + 4 * j);
    };
    auto loadB = [&](int k0) {
        const float* r = Bbase + (long long)aRow * ldb + k0 + aOff;
#pragma unroll
        for (int j = 0; j < 4; j++) pb[j] = *(const float4*)(r + 4 * j);
    };
    auto storeAB = [&](int buf) {
        __half* Ab = As + buf * 128 * 40;
        __half* Bb = Bs + buf * 128 * 40;
#pragma unroll
        for (int j = 0; j < 4; j++) {
            *(__half2*)&Ab[aRow * 40 + aOff + 4 * j]     = __floats2half2_rn(pa[j].x, pa[j].y);
            *(__half2*)&Ab[aRow * 40 + aOff + 4 * j + 2] = __floats2half2_rn(pa[j].z, pa[j].w);
            *(__half2*)&Bb[aRow * 40 + aOff + 4 * j]     = __floats2half2_rn(pb[j].x, pb[j].y);
            *(__half2*)&Bb[aRow * 40 + aOff + 4 * j + 2] = __floats2half2_rn(pb[j].z, pb[j].w);
        }
    };

    float c[4][4][4];
#pragma unroll
    for (int mi = 0; mi < 4; mi++)
#pragma unroll
        for (int ni = 0; ni < 4; ni++)
#pragma unroll
            for (int r = 0; r < 4; r++) c[mi][ni][r] = 0.0f;

    loadA(0); loadB(0);
    storeAB(0);
    __syncthreads();

    const int nst = K / 32;
    for (int s = 0; s < nst; s++) {
        const int buf = s & 1;
        const __half* Ab = As + buf * 128 * 40;
        const __half* Bb = Bs + buf * 128 * 40;
        if (s + 1 < nst) { loadA((s + 1) * 32); loadB((s + 1) * 32); }
#pragma unroll
        for (int ks = 0; ks < 2; ks++) {
            const int kb = ks * 16;
            unsigned a[4][4], b[4][2];
#pragma unroll
            for (int mi = 0; mi < 4; mi++) {
                int r0 = wm + mi * 16 + gid;
                a[mi][0] = *(const unsigned*)&Ab[r0 * 40 + kb + 2 * ctig];
                a[mi][1] = *(const unsigned*)&Ab[(r0 + 8) * 40 + kb + 2 * ctig];
                a[mi][2] = *(const unsigned*)&Ab[r0 * 40 + kb + 8 + 2 * ctig];
                a[mi][3] = *(const unsigned*)&Ab[(r0 + 8) * 40 + kb + 8 + 2 * ctig];
            }
#pragma unroll
            for (int ni = 0; ni < 4; ni++) {
                int cc = wn + ni * 8 + gid;
                b[ni][0] = *(const unsigned*)&Bb[cc * 40 + kb + 2 * ctig];
                b[ni][1] = *(const unsigned*)&Bb[cc * 40 + kb + 8 + 2 * ctig];
            }
#pragma unroll
            for (int mi = 0; mi < 4; mi++)
#pragma unroll
                for (int ni = 0; ni < 4; ni++) {
                    asm volatile(
                        "mma.sync.aligned.m16n8k16.row.col.f32.f16.f16.f32 "
                        "{%0,%1,%2,%3}, {%4,%5,%6,%7}, {%8,%9}, {%0,%1,%2,%3};\n"
                        : "+f"(c[mi][ni][0]), "+f"(c[mi][ni][1]),
                          "+f"(c[mi][ni][2]), "+f"(c[mi][ni][3])
                        : "r"(a[mi][0]), "r"(a[mi][1]), "r"(a[mi][2]), "r"(a[mi][3]),
                          "r"(b[ni][0]), "r"(b[ni][1]));
                }
        }
        if (s + 1 < nst) storeAB(buf ^ 1);
        __syncthreads();
    }

    const int Mtot = gridDim.y * 128;
    const float* rnp = (EPI == 1) ? (rn + z * Mtot + (long long)blockIdx.y * 128) : nullptr;
    const float* cnp = (EPI == 1) ? (cn + z * N + blockIdx.x * 128) : nullptr;
#pragma unroll
    for (int mi = 0; mi < 4; mi++) {
#pragma unroll
        for (int half = 0; half < 2; half++) {
            int r = wm + mi * 16 + gid + half * 8;
            float rvv = (EPI == 1) ? rnp[r] : 0.0f;
#pragma unroll
            for (int ni = 0; ni < 4; ni++) {
                int cc = wn + ni * 8 + 2 * ctig;
                float v0 = c[mi][ni][half * 2 + 0];
                float v1 = c[mi][ni][half * 2 + 1];
                if (EPI == 1) {
                    v0 = sqrtf(fmaxf(rvv + cnp[cc]     - 2.0f * v0, 0.0f));
                    v1 = sqrtf(fmaxf(rvv + cnp[cc + 1] - 2.0f * v1, 0.0f));
                } else if (EPI == 2) {
                    v0 = fmaxf(v0, 0.0f);
                    v1 = fmaxf(v1, 0.0f);
                }
                *(float2*)(Cbase + (long long)r * N + cc) = make_float2(v0, v1);
            }
        }
    }
#endif
}

// ---------------- reductions ----------------
__device__ __forceinline__ float warpReduceSum(float v) {
    v += __shfl_xor_sync(0xffffffffu, v, 16);
    v += __shfl_xor_sync(0xffffffffu, v, 8);
    v += __shfl_xor_sync(0xffffffffu, v, 4);
    v += __shfl_xor_sync(0xffffffffu, v, 2);
    v += __shfl_xor_sync(0xffffffffu, v, 1);
    return v;
}
__device__ __forceinline__ float warpReduceMax(float v) {
    v = fmaxf(v, __shfl_xor_sync(0xffffffffu, v, 16));
    v = fmaxf(v, __shfl_xor_sync(0xffffffffu, v, 8));
    v = fmaxf(v, __shfl_xor_sync(0xffffffffu, v, 4));
    v = fmaxf(v, __shfl_xor_sync(0xffffffffu, v, 2));
    v = fmaxf(v, __shfl_xor_sync(0xffffffffu, v, 1));
    return v;
}
__device__ __forceinline__ float blockAllReduceSum(float v, float* sh) {
    int lane = threadIdx.x & 31, wid = threadIdx.x >> 5;
    v = warpReduceSum(v);
    if (lane == 0) sh[wid] = v;
    __syncthreads();
    int nw = blockDim.x >> 5;
    float t = (lane < nw) ? sh[lane] : 0.0f;
    t = warpReduceSum(t);
    __syncthreads();
    return t;
}
__device__ __forceinline__ float blockAllReduceMax(float v, float* sh) {
    int lane = threadIdx.x & 31, wid = threadIdx.x >> 5;
    v = warpReduceMax(v);
    if (lane == 0) sh[wid] = v;
    __syncthreads();
    int nw = blockDim.x >> 5;
    float t = (lane < nw) ? sh[lane] : -3.0e38f;
    t = warpReduceMax(t);
    __syncthreads();
    return t;
}

// ---------------- tf32 pre-round: out[i] = tf32(in[i]) ----------------
__global__ __launch_bounds__(256)
void round_kernel(const float* __restrict__ in, float* __restrict__ out, int n4)
{
    int i = blockIdx.x * 256 + threadIdx.x;
    if (i < n4) {
        float4 v = *(const float4*)(in + 4 * (long long)i);
        v.x = to_tf32(v.x); v.y = to_tf32(v.y);
        v.z = to_tf32(v.z); v.w = to_tf32(v.w);
        *(float4*)(out + 4 * (long long)i) = v;
    }
}

// ---------------- fp32 transpose + tf32 round (R,C multiples of 32) ----------
__global__ __launch_bounds__(256)
void transpose_kernel(const float* __restrict__ in, float* __restrict__ out,
                      int R, int C)
{
    __shared__ float t[32][33];
    int bx = blockIdx.x * 32, by = blockIdx.y * 32;
    int x = bx + threadIdx.x;
#pragma unroll
    for (int j = 0; j < 32; j += 8)
        t[threadIdx.y + j][threadIdx.x] = in[(long long)(by + threadIdx.y + j) * C + x];
    __syncthreads();
    int x2 = by + threadIdx.x;
#pragma unroll
    for (int j = 0; j < 32; j += 8)
        out[(long long)(bx + threadIdx.y + j) * R + x2] = to_tf32(t[threadIdx.x][threadIdx.y + j]);
}

// ---------------- row squared-norm ----------------
__global__ __launch_bounds__(128)
void rownorm2_kernel(const float* __restrict__ X, float* __restrict__ out)
{
    __shared__ float sh[32];
    long long row = blockIdx.x;
    const float* x = X + row * DD;
    float4 v = *(const float4*)(x + threadIdx.x * 4);
    float s = v.x * v.x + v.y * v.y + v.z * v.z + v.w * v.w;
    s = blockAllReduceSum(s, sh);
    if (threadIdx.x == 0) out[row] = s;
}

// ---------------- softmax over S=4096, in place, tf32-rounded output -------
__global__ __launch_bounds__(256)
void softmax_rows_kernel()
{
    __shared__ float sh[32];
    long long row = blockIdx.x;
    float* p = g_s + row * SSEQ;
    int t = threadIdx.x;

    float4 f[4];
    float mx = -3.0e38f;
#pragma unroll
    for (int i = 0; i < 4; i++) {
        f[i] = *(const float4*)(p + i * 1024 + t * 4);
        mx = fmaxf(mx, fmaxf(fmaxf(f[i].x, f[i].y), fmaxf(f[i].z, f[i].w)));
    }
    mx = blockAllReduceMax(mx, sh);

    float sum = 0.0f;
#pragma unroll
    for (int i = 0; i < 4; i++) {
        f[i].x = __expf(f[i].x - mx);
        f[i].y = __expf(f[i].y - mx);
        f[i].z = __expf(f[i].z - mx);
        f[i].w = __expf(f[i].w - mx);
        sum += f[i].x + f[i].y + f[i].z + f[i].w;
    }
    sum = blockAllReduceSum(sum, sh);
    float r = 1.0f / sum;
#pragma unroll
    for (int i = 0; i < 4; i++) {
        f[i].x = to_tf32(f[i].x * r); f[i].y = to_tf32(f[i].y * r);
        f[i].z = to_tf32(f[i].z * r); f[i].w = to_tf32(f[i].w * r);
        *(float4*)(p + i * 1024 + t * 4) = f[i];
    }
}

// ---------------- LayerNorm over D=512 (+ optional residual / tf32 round) ---
__global__ __launch_bounds__(128)
void layernorm_kernel(const float* __restrict__ X, const float* __restrict__ G,
                      const float* __restrict__ Bv, const float* __restrict__ R,
                      float* __restrict__ O, int rnd)
{
    __shared__ float sh[32];
    long long row = blockIdx.x;
    int c = threadIdx.x * 4;
    float4 v = *(const float4*)(X + row * DD + c);

    float s = v.x + v.y + v.z + v.w;
    s = blockAllReduceSum(s, sh);
    float mu = s * (1.0f / DD);

    float d0 = v.x - mu, d1 = v.y - mu, d2 = v.z - mu, d3 = v.w - mu;
    float s2 = d0 * d0 + d1 * d1 + d2 * d2 + d3 * d3;
    s2 = blockAllReduceSum(s2, sh);
    float inv = rsqrtf(s2 * (1.0f / DD) + 1e-5f);

    float4 gg = *(const float4*)(G + c);
    float4 bb = *(const float4*)(Bv + c);
    float4 o;
    o.x = d0 * inv * gg.x + bb.x;
    o.y = d1 * inv * gg.y + bb.y;
    o.z = d2 * inv * gg.z + bb.z;
    o.w = d3 * inv * gg.w + bb.w;
    if (R) {
        float4 rr = *(const float4*)(R + row * DD + c);
        o.x += rr.x; o.y += rr.y; o.z += rr.z; o.w += rr.w;
    }
    if (rnd) {
        o.x = to_tf32(o.x); o.y = to_tf32(o.y);
        o.z = to_tf32(o.z); o.w = to_tf32(o.w);
    }
    *(float4*)(O + row * DD + c) = o;
}

// ======================================================================
#define SMEM_BYTES 98304   // 3 x 32KB ring -> 2 CTAs/SM

extern "C" void kernel_launch(void* const* d_in, const int* in_sizes, int n_in,
                              void* d_out, int out_size)
{
    (void)in_sizes; (void)n_in; (void)out_size;
    const float* x   = (const float*)d_in[0];
    const float* src = (const float*)d_in[1];
    const float* Wq  = (const float*)d_in[2];
    const float* Wk  = (const float*)d_in[3];
    const float* Wv  = (const float*)d_in[4];
    const float* Wm  = (const float*)d_in[5];
    const float* W1  = (const float*)d_in[6];
    const float* W2  = (const float*)d_in[7];
    const float* g1  = (const float*)d_in[8];
    const float* b1  = (const float*)d_in[9];
    const float* g2  = (const float*)d_in[10];
    const float* b2  = (const float*)d_in[11];
    float* out = (float*)d_out;

    float *q, *k, *vT, *q2, *k2, *sc, *msg, *mw, *mln, *hid, *ffn, *wt, *xr, *srcr;
    cudaGetSymbolAddress((void**)&q,    g_q);
    cudaGetSymbolAddress((void**)&k,    g_k);
    cudaGetSymbolAddress((void**)&vT,   g_vT);
    cudaGetSymbolAddress((void**)&q2,   g_q2);
    cudaGetSymbolAddress((void**)&k2,   g_k2);
    cudaGetSymbolAddress((void**)&sc,   g_s);
    cudaGetSymbolAddress((void**)&msg,  g_msg);
    cudaGetSymbolAddress((void**)&mw,   g_mw);
    cudaGetSymbolAddress((void**)&mln,  g_mln);
    cudaGetSymbolAddress((void**)&hid,  g_hid);
    cudaGetSymbolAddress((void**)&ffn,  g_ffn);
    cudaGetSymbolAddress((void**)&wt,   g_wt);
    cudaGetSymbolAddress((void**)&xr,   g_xr);
    cudaGetSymbolAddress((void**)&srcr, g_srcr);

    float* WqT = wt;
    float* WkT = wt + DD * DD;
    float* WvT = wt + 2 * DD * DD;
    float* WmT = wt + 3 * DD * DD;
    float* W1T = wt + 4 * DD * DD;
    float* W2T = wt + 8 * DD * DD;

    cudaFuncSetAttribute(tc_gemm<0,0,0>, cudaFuncAttributeMaxDynamicSharedMemorySize, SMEM_BYTES);
    cudaFuncSetAttribute(tc_gemm<0,0,1>, cudaFuncAttributeMaxDynamicSharedMemorySize, SMEM_BYTES);
    cudaFuncSetAttribute(tc_gemm<1,0,0>, cudaFuncAttributeMaxDynamicSharedMemorySize, SMEM_BYTES);
    cudaFuncSetAttribute(tc_gemm<2,1,1>, cudaFuncAttributeMaxDynamicSharedMemorySize, SMEM_BYTES);

    // 0a. pre-round raw inputs once (removes all in-loop cvt)
    round_kernel<<<(NB * LQ * DD / 4 + 255) / 256,   256>>>(x,   xr,   NB * LQ * DD / 4);
    round_kernel<<<(NB * SSEQ * DD / 4 + 255) / 256, 256>>>(src, srcr, NB * SSEQ * DD / 4);
    // 0b. transpose weights (rounded at write)
    transpose_kernel<<<dim3(16, 16), dim3(32, 8)>>>(Wq, WqT, DD, DD);
    transpose_kernel<<<dim3(16, 16), dim3(32, 8)>>>(Wk, WkT, DD, DD);
    transpose_kernel<<<dim3(16, 16), dim3(32, 8)>>>(Wv, WvT, DD, DD);
    transpose_kernel<<<dim3(16, 16), dim3(32, 8)>>>(Wm, WmT, DD, DD);
    transpose_kernel<<<dim3(32, 32), dim3(32, 8)>>>(W1, W1T, 2 * DD, 2 * DD);
    transpose_kernel<<<dim3(16, 32), dim3(32, 8)>>>(W2, W2T, 2 * DD, DD);

    // 1. projections (outputs rounded: consumed by later GEMMs)
    tc_gemm<0,0,1><<<dim3(4, 64, 1),  256, SMEM_BYTES>>>(xr,   nullptr, WqT, q, DD, DD, DD, DD, 0, 0, 0, nullptr, nullptr);
    tc_gemm<0,0,1><<<dim3(4, 256, 1), 256, SMEM_BYTES>>>(srcr, nullptr, WkT, k, DD, DD, DD, DD, 0, 0, 0, nullptr, nullptr);
    tc_gemm<0,0,1><<<dim3(SSEQ / 128, DD / 128, NB), 256, SMEM_BYTES>>>(
        WvT, nullptr, srcr, vT, SSEQ, DD, DD, DD,
        0, (long long)SSEQ * DD, (long long)DD * SSEQ, nullptr, nullptr);

    // 2. squared row norms (on rounded q,k -> exact distance identity)
    rownorm2_kernel<<<NB * LQ,   128>>>(q, q2);
    rownorm2_kernel<<<NB * SSEQ, 128>>>(k, k2);

    // 3. distances: sc = sqrt(max(q2 + k2 - 2 q.k, 0))
    tc_gemm<1,0,0><<<dim3(SSEQ / 128, LQ / 128, NB), 256, SMEM_BYTES>>>(
        q, nullptr, k, sc, SSEQ, DD, DD, DD,
        (long long)LQ * DD, (long long)SSEQ * DD, (long long)LQ * SSEQ, q2, k2);

    // 4. softmax over S (in place, rounded output)
    softmax_rows_kernel<<<NB * LQ, 256>>>();

    // 5. message = attn @ v  (rounded output: feeds Wm GEMM)
    tc_gemm<0,0,1><<<dim3(4, LQ / 128, NB), 256, SMEM_BYTES>>>(
        sc, nullptr, vT, msg, DD, SSEQ, SSEQ, SSEQ,
        (long long)LQ * SSEQ, (long long)DD * SSEQ, (long long)LQ * DD, nullptr, nullptr);

    // 6. mw = message @ Wm ; mln = LN(mw) rounded (feeds hid GEMM)
    tc_gemm<0,0,0><<<dim3(4, 64, 1), 256, SMEM_BYTES>>>(msg, nullptr, WmT, mw, DD, DD, DD, DD, 0, 0, 0, nullptr, nullptr);
    layernorm_kernel<<<NB * LQ, 128>>>(mw, g1, b1, nullptr, mln, 1);

    // 7. hid = relu([x, mln] @ W1), rounded (feeds ffn GEMM)
    tc_gemm<2,1,1><<<dim3(8, 64, 1), 256, SMEM_BYTES>>>(xr, mln, W1T, hid, 2 * DD, 2 * DD, DD, 2 * DD, 0, 0, 0, nullptr, nullptr);

    // 8. ffn = hid @ W2
    tc_gemm<0,0,0><<<dim3(4, 64, 1), 256, SMEM_BYTES>>>(hid, nullptr, W2T, ffn, DD, 2 * DD, 2 * DD, 2 * DD, 0, 0, 0, nullptr, nullptr);

    // 9. out = x + LN(ffn)  (residual uses ORIGINAL x, no rounding)
    layernorm_kernel<<<NB * LQ, 128>>>(ffn, g2, b2, x, out, 0);
}

// round 9
// speedup vs baseline: 3.3535x; 1.2222x over previous
#include <cuda_runtime.h>
#include <cuda_fp16.h>
#include <cstdint>

// Problem dims (fixed)
#define NB   8
#define LQ   1024
#define SSEQ 4096
#define DD   512

#ifndef __CUDA_ARCH_SPECIFIC__
#define __CUDA_ARCH_SPECIFIC__ 0
#endif
#if defined(__CUDA_ARCH_FEAT_SM103_ALL) || defined(__CUDA_ARCH_FEAT_SM100_ALL) || (__CUDA_ARCH_SPECIFIC__ >= 1000)
#define HAS_TCGEN05 1
#else
#define HAS_TCGEN05 0
#endif

// ---------------- static device scratch (no allocations allowed) ----------------
static __device__ float g_q  [NB * LQ * DD];
static __device__ float g_k  [NB * SSEQ * DD];
static __device__ float g_vT [NB * DD * SSEQ];
static __device__ float g_q2 [NB * LQ];
static __device__ float g_k2 [NB * SSEQ];
static __device__ float g_ssum[NB * LQ];              // row sums of exp(dist)
static __device__ float g_s  [NB * LQ * SSEQ];        // exp(dist), unnormalized
static __device__ float g_msg[NB * LQ * DD];
static __device__ float g_mw [NB * LQ * DD];
static __device__ float g_mln[NB * LQ * DD];
static __device__ float g_hid[NB * LQ * 2 * DD];
static __device__ float g_ffn[NB * LQ * DD];
static __device__ float g_wt [4 * DD * DD + 2 * DD * 2 * DD + 2 * DD * DD];
static __device__ float g_xr [NB * LQ * DD];
static __device__ float g_srcr[NB * SSEQ * DD];

// ======================= PTX helpers =======================
__device__ __forceinline__ uint32_t smem_u32(const void* p) {
    uint32_t a;
    asm("{ .reg .u64 t; cvta.to.shared.u64 t, %1; cvt.u32.u64 %0, t; }" : "=r"(a) : "l"(p));
    return a;
}
__device__ __forceinline__ float to_tf32(float x) {
    float r;
    asm("cvt.rna.tf32.f32 %0, %1;" : "=f"(r) : "f"(x));
    return r;
}
#define CP_ASYNC16(dst, src) \
    asm volatile("cp.async.cg.shared.global [%0], [%1], 16;" :: "r"(dst), "l"(src) : "memory")
#define CP_COMMIT() asm volatile("cp.async.commit_group;" ::: "memory")
#define CP_WAIT1()  asm volatile("cp.async.wait_group 1;" ::: "memory")
#define CP_WAIT0()  asm volatile("cp.async.wait_group 0;" ::: "memory")

#if HAS_TCGEN05
__device__ __forceinline__ uint32_t elect_one() {
    uint32_t pred;
    asm volatile("{\n\t.reg .pred p;\n\telect.sync _|p, 0xFFFFFFFF;\n\t"
                 "selp.b32 %0, 1, 0, p;\n\t}" : "=r"(pred));
    return pred;
}
#define MBAR_INIT(addr, cnt) \
    asm volatile("mbarrier.init.shared.b64 [%0], %1;" :: "r"(addr), "r"(cnt) : "memory")
#define MBAR_INVAL(addr) \
    asm volatile("mbarrier.inval.shared.b64 [%0];" :: "r"(addr) : "memory")
__device__ __forceinline__ void mbar_wait(uint32_t addr, uint32_t parity) {
    uint32_t done;
    asm volatile("{\n\t.reg .pred p;\n\t"
                 "mbarrier.try_wait.parity.acquire.cta.shared::cta.b64 p, [%1], %2;\n\t"
                 "selp.b32 %0, 1, 0, p;\n\t}" : "=r"(done) : "r"(addr), "r"(parity) : "memory");
    if (!done) {
        asm volatile("{\n\t.reg .pred P1;\n\t"
                     "W_%=:\n\t"
                     "mbarrier.try_wait.parity.acquire.cta.shared::cta.b64 P1, [%0], %1, 0x989680;\n\t"
                     "@P1 bra.uni D_%=;\n\t"
                     "bra.uni W_%=;\n\t"
                     "D_%=:\n\t}" :: "r"(addr), "r"(parity) : "memory");
    }
}
#define TC_ALLOC(smem_addr, n) \
    asm volatile("tcgen05.alloc.cta_group::1.sync.aligned.shared::cta.b32 [%0], %1;" \
                 :: "r"(smem_addr), "r"(n) : "memory")
#define TC_DEALLOC(tmem, n) \
    asm volatile("tcgen05.dealloc.cta_group::1.sync.aligned.b32 %0, %1;" :: "r"(tmem), "r"(n))
#define TC_RELINQ() \
    asm volatile("tcgen05.relinquish_alloc_permit.cta_group::1.sync.aligned;")
#define TC_COMMIT(mbar) \
    asm volatile("tcgen05.commit.cta_group::1.mbarrier::arrive::one.shared::cluster.b64 [%0];" \
                 :: "r"(mbar) : "memory")
#define TC_FENCE_AFTER() asm volatile("tcgen05.fence::after_thread_sync;" ::: "memory")
#define TC_WAIT_LD()     asm volatile("tcgen05.wait::ld.sync.aligned;" ::: "memory")
#define FENCE_ASYNC()    asm volatile("fence.proxy.async.shared::cta;" ::: "memory")

__device__ __forceinline__ void mma_tf32_ss(uint32_t d, uint64_t a, uint64_t b,
                                            uint32_t idesc, uint32_t en) {
    asm volatile("{\n\t.reg .pred p;\n\tsetp.ne.u32 p, %4, 0;\n\t"
                 "tcgen05.mma.cta_group::1.kind::tf32 [%0], %1, %2, %3, {%5,%5,%5,%5}, p;\n\t}"
                 :: "r"(d), "l"(a), "l"(b), "r"(idesc), "r"(en), "r"(0u) : "memory");
}
__device__ __forceinline__ void tmem_ld_x32(uint32_t* r, uint32_t addr) {
    asm volatile(
        "tcgen05.ld.sync.aligned.32x32b.x32.b32 "
        "{%0,%1,%2,%3,%4,%5,%6,%7,%8,%9,%10,%11,%12,%13,%14,%15,"
        "%16,%17,%18,%19,%20,%21,%22,%23,%24,%25,%26,%27,%28,%29,%30,%31}, [%32];"
        : "=r"(r[0]), "=r"(r[1]), "=r"(r[2]), "=r"(r[3]), "=r"(r[4]), "=r"(r[5]),
          "=r"(r[6]), "=r"(r[7]), "=r"(r[8]), "=r"(r[9]), "=r"(r[10]), "=r"(r[11]),
          "=r"(r[12]), "=r"(r[13]), "=r"(r[14]), "=r"(r[15]), "=r"(r[16]), "=r"(r[17]),
          "=r"(r[18]), "=r"(r[19]), "=r"(r[20]), "=r"(r[21]), "=r"(r[22]), "=r"(r[23]),
          "=r"(r[24]), "=r"(r[25]), "=r"(r[26]), "=r"(r[27]), "=r"(r[28]), "=r"(r[29]),
          "=r"(r[30]), "=r"(r[31])
        : "r"(addr));
}
__device__ __forceinline__ uint32_t sw128(uint32_t b) { return b ^ ((b >> 3) & 0x70); }
static __device__ __forceinline__ uint64_t make_desc(uint32_t addr) {
    const uint64_t base = (uint64_t(2) << 61) | (uint64_t(1) << 46)
                        | (uint64_t(64) << 32) | (uint64_t(1) << 16);
    return base | ((uint64_t)(addr >> 4) & 0x3FFF);
}
#define IDESC_TF32 ((1u << 4) | (2u << 7) | (2u << 10) | ((128u / 8u) << 17) | ((128u / 16u) << 24))
#endif  // HAS_TCGEN05

// ======================================================================
// NT GEMM: C[M,N] = A[M,K] * Bt[N,K]^T, fp32 accumulate.
// CTA tile 128(M) x 256(N). tcgen05 path:
//   - 2-slot smem ring, slot = A(16KB) + B0(16KB) + B1(16KB) = 48KB -> 2 CTAs/SM
//   - cp.async 16B loader (no register staging), commit-group pipeline depth 2
//   - per stage: 8 MMA dispatches (4 K-chunks x 2 N-halves, TMEM cols 0/128)
// EPI: 0 none, 1 exp(sqrt(max(rn+cn-2acc,0))) + atomic row-sum, 2 relu,
//      3 divide by rn[row].  ROUND: tf32-round C at store.
// DUAL: A logical K = 2*512, first half gA, second gA2 (both lda=512).
// ======================================================================
template<int EPI, int DUAL, int ROUND>
__global__ __launch_bounds__(256)
void tc_gemm(const float* __restrict__ gA, const float* __restrict__ gA2,
             const float* __restrict__ gB, float* __restrict__ gC,
             int N, int K, int lda, int ldb,
             long long sA, long long sB, long long sC,
             const float* __restrict__ rn, const float* __restrict__ cn,
             float* __restrict__ sum)
{
    extern __shared__ __align__(1024) char dyn_smem[];

    const int tid = threadIdx.x;
    const int wid = tid >> 5, lane = tid & 31;

    const long long z = blockIdx.z;
    const float* Abase  = gA + z * sA + (long long)blockIdx.y * 128 * lda;
    const float* A2base = DUAL ? (gA2 + (long long)blockIdx.y * 128 * lda) : nullptr;
    const float* Bbase  = gB + z * sB + (long long)blockIdx.x * 256 * ldb;
    float* Cbase = gC + z * sC + (long long)blockIdx.y * 128 * N + blockIdx.x * 256;
    const int Mtot = gridDim.y * 128;

#if HAS_TCGEN05
    __shared__ uint32_t s_tmem[1];
    __shared__ __align__(8) uint64_t s_mbar[2];

    const uint32_t smem_base = smem_u32(dyn_smem);
    const uint32_t mbar_base = smem_u32(&s_mbar[0]);

    if (wid == 0) {
        TC_ALLOC(smem_u32(s_tmem), 256);
        TC_RELINQ();
    }
    if (tid == 0) { MBAR_INIT(mbar_base, 1); MBAR_INIT(mbar_base + 8, 1); }
    __syncthreads();
    const uint32_t tmem = s_tmem[0];

    // loader geometry: rows of 32 floats = 128B, SW128
    const int r0 = tid >> 3, c0 = tid & 7;

    auto cp_stage = [&](int s) {
        const int slot = s & 1;
        const uint32_t sbase = smem_base + slot * 49152;
        const int k0 = s * 32;
        const float* Ap = DUAL ? (k0 < 512 ? Abase + k0 : A2base + (k0 - 512)) : (Abase + k0);
        const float* Bp = Bbase + k0;
#pragma unroll
        for (int j = 0; j < 4; j++) {
            int row = r0 + j * 32;
            CP_ASYNC16(sbase + sw128((uint32_t)(row * 128 + c0 * 16)),
                       Ap + (long long)row * lda + c0 * 4);
        }
#pragma unroll
        for (int j = 0; j < 8; j++) {
            int row = r0 + j * 32;                 // 0..255
            uint32_t off = (j < 4) ? (16384u + sw128((uint32_t)(row * 128 + c0 * 16)))
                                   : (32768u + sw128((uint32_t)((row - 128) * 128 + c0 * 16)));
            CP_ASYNC16(sbase + off, Bp + (long long)row * ldb + c0 * 4);
        }
        CP_COMMIT();
    };

    const int nst = K / 32;                        // 16 / 32 / 128
    cp_stage(0);
    cp_stage(1);
    for (int s = 0; s < nst; s++) {
        const int slot = s & 1;
        if (s == nst - 1) CP_WAIT0(); else CP_WAIT1();
        __syncthreads();
        if (wid == 0) {
            FENCE_ASYNC();
            if (elect_one()) {
                uint32_t aAddr = smem_base + slot * 49152;
                uint64_t ad  = make_desc(aAddr);
                uint64_t bd0 = make_desc(aAddr + 16384);
                uint64_t bd1 = make_desc(aAddr + 32768);
#pragma unroll
                for (int st = 0; st < 4; st++) {
                    uint32_t en = (s > 0 || st > 0) ? 1u : 0u;
                    mma_tf32_ss(tmem,       ad + st * 2, bd0 + st * 2, IDESC_TF32, en);
                    mma_tf32_ss(tmem + 128, ad + st * 2, bd1 + st * 2, IDESC_TF32, en);
                }
                TC_COMMIT(mbar_base + slot * 8);
            }
        }
        if (s + 2 < nst) {
            mbar_wait(mbar_base + slot * 8, (s >> 1) & 1);   // stage s MMA done
            cp_stage(s + 2);
        }
    }
    {   // drain: commit of last stage covers all prior MMAs
        const int L = nst - 1;
        mbar_wait(mbar_base + (L & 1) * 8, (L >> 1) & 1);
    }
    TC_FENCE_AFTER();

    // ---------------- epilogue ----------------
    float* stg = (float*)dyn_smem;                 // [128][33] staging
    float rv = 0.0f, rinv = 0.0f, psum = 0.0f, cnv = 0.0f;
    if (wid < 4) {
        int rowg = (int)(z * Mtot) + blockIdx.y * 128 + wid * 32 + lane;
        if (EPI == 1) rv = rn[rowg];
        if (EPI == 3) rinv = 1.0f / rn[rowg];
    }

#pragma unroll
    for (int ch = 0; ch < 8; ch++) {
        if (wid < 4) {
            uint32_t r[32];
            tmem_ld_x32(r, tmem + ch * 32);
            TC_WAIT_LD();
            if (EPI == 1) cnv = cn[z * N + (long long)blockIdx.x * 256 + ch * 32 + lane];
            int row = wid * 32 + lane;
#pragma unroll
            for (int c = 0; c < 32; c++) {
                float v = __uint_as_float(r[c]);
                if (EPI == 1) {
                    float cc = __shfl_sync(0xffffffffu, cnv, c);
                    v = __expf(sqrtf(fmaxf(rv + cc - 2.0f * v, 0.0f)));
                } else if (EPI == 2) {
                    v = fmaxf(v, 0.0f);
                } else if (EPI == 3) {
                    v *= rinv;
                }
                if (ROUND) v = to_tf32(v);
                if (EPI == 1) psum += v;
                stg[row * 33 + c] = v;
            }
        }
        __syncthreads();
#pragma unroll
        for (int it = 0; it < 16; it++) {
            int row = wid + it * 8;
            Cbase[(long long)row * N + ch * 32 + lane] = stg[row * 33 + lane];
        }
        __syncthreads();
    }
    if (EPI == 1 && wid < 4) {
        int rowg = (int)(z * Mtot) + blockIdx.y * 128 + wid * 32 + lane;
        atomicAdd(&sum[rowg], psum);
    }

    if (tid == 0) { MBAR_INVAL(mbar_base); MBAR_INVAL(mbar_base + 8); }
    __syncthreads();
    if (wid == 0) TC_DEALLOC(tmem, 256);

#else
    // ---------------- fp16 mma.sync fallback (never runs on GB300) ----------------
    __half* As = (__half*)dyn_smem;
    __half* Bs = (__half*)dyn_smem + 2 * 128 * 40;

    const int gid = lane >> 2, ctig = lane & 3;
    const int wm = (wid & 1) * 64;
    const int wn = (wid >> 1) * 32;
    const int aRow = tid >> 1;
    const int aOff = (tid & 1) * 16;

    for (int nh = 0; nh < 2; nh++) {
        const float* BbaseH = Bbase + (long long)nh * 128 * ldb;
        float* CbaseH = Cbase + nh * 128;
        __syncthreads();

        float4 pa[4], pb[4];
        auto loadA = [&](int k0) {
            const float* Ap = DUAL ? (k0 < 512 ? Abase + k0 : A2base + (k0 - 512)) : (Abase + k0);
            const float* r = Ap + (long long)aRow * lda + aOff;
#pragma unroll
            for (int j = 0; j < 4; j++) pa[j] = *(const float4*)(r + 4 * j);
        };
        auto loadB = [&](int k0) {
            const float* r = BbaseH + (long long)aRow * ldb + k0 + aOff;
#pragma unroll
            for (int j = 0; j < 4; j++) pb[j] = *(const float4*)(r + 4 * j);
        };
        auto storeAB = [&](int buf) {
            __half* Ab = As + buf * 128 * 40;
            __half* Bb = Bs + buf * 128 * 40;
#pragma unroll
            for (int j = 0; j < 4; j++) {
                *(__half2*)&Ab[aRow * 40 + aOff + 4 * j]     = __floats2half2_rn(pa[j].x, pa[j].y);
                *(__half2*)&Ab[aRow * 40 + aOff + 4 * j + 2] = __floats2half2_rn(pa[j].z, pa[j].w);
                *(__half2*)&Bb[aRow * 40 + aOff + 4 * j]     = __floats2half2_rn(pb[j].x, pb[j].y);
                *(__half2*)&Bb[aRow * 40 + aOff + 4 * j + 2] = __floats2half2_rn(pb[j].z, pb[j].w);
            }
        };

        float c[4][4][4];
#pragma unroll
        for (int mi = 0; mi < 4; mi++)
#pragma unroll
            for (int ni = 0; ni < 4; ni++)
#pragma unroll
                for (int r = 0; r < 4; r++) c[mi][ni][r] = 0.0f;

        loadA(0); loadB(0);
        storeAB(0);
        __syncthreads();

        const int nst = K / 32;
        for (int s = 0; s < nst; s++) {
            const int buf = s & 1;
            const __half* Ab = As + buf * 128 * 40;
            const __half* Bb = Bs + buf * 128 * 40;
            if (s + 1 < nst) { loadA((s + 1) * 32); loadB((s + 1) * 32); }
#pragma unroll
            for (int ks = 0; ks < 2; ks++) {
                const int kb = ks * 16;
                unsigned a[4][4], b[4][2];
#pragma unroll
                for (int mi = 0; mi < 4; mi++) {
                    int r0 = wm + mi * 16 + gid;
                    a[mi][0] = *(const unsigned*)&Ab[r0 * 40 + kb + 2 * ctig];
                    a[mi][1] = *(const unsigned*)&Ab[(r0 + 8) * 40 + kb + 2 * ctig];
                    a[mi][2] = *(const unsigned*)&Ab[r0 * 40 + kb + 8 + 2 * ctig];
                    a[mi][3] = *(const unsigned*)&Ab[(r0 + 8) * 40 + kb + 8 + 2 * ctig];
                }
#pragma unroll
                for (int ni = 0; ni < 4; ni++) {
                    int cc = wn + ni * 8 + gid;
                    b[ni][0] = *(const unsigned*)&Bb[cc * 40 + kb + 2 * ctig];
                    b[ni][1] = *(const unsigned*)&Bb[cc * 40 + kb + 8 + 2 * ctig];
                }
#pragma unroll
                for (int mi = 0; mi < 4; mi++)
#pragma unroll
                    for (int ni = 0; ni < 4; ni++) {
                        asm volatile(
                            "mma.sync.aligned.m16n8k16.row.col.f32.f16.f16.f32 "
                            "{%0,%1,%2,%3}, {%4,%5,%6,%7}, {%8,%9}, {%0,%1,%2,%3};\n"
                            : "+f"(c[mi][ni][0]), "+f"(c[mi][ni][1]),
                              "+f"(c[mi][ni][2]), "+f"(c[mi][ni][3])
                            : "r"(a[mi][0]), "r"(a[mi][1]), "r"(a[mi][2]), "r"(a[mi][3]),
                              "r"(b[ni][0]), "r"(b[ni][1]));
                    }
            }
            if (s + 1 < nst) storeAB(buf ^ 1);
            __syncthreads();
        }

        const float* rnp = (EPI == 1 || EPI == 3) ? (rn + z * Mtot + (long long)blockIdx.y * 128) : nullptr;
        const float* cnp = (EPI == 1) ? (cn + z * N + blockIdx.x * 256 + nh * 128) : nullptr;
#pragma unroll
        for (int mi = 0; mi < 4; mi++) {
#pragma unroll
            for (int half = 0; half < 2; half++) {
                int r = wm + mi * 16 + gid + half * 8;
                float rvv = (EPI == 1 || EPI == 3) ? rnp[r] : 0.0f;
#pragma unroll
                for (int ni = 0; ni < 4; ni++) {
                    int cc = wn + ni * 8 + 2 * ctig;
                    float v0 = c[mi][ni][half * 2 + 0];
                    float v1 = c[mi][ni][half * 2 + 1];
                    if (EPI == 1) {
                        v0 = __expf(sqrtf(fmaxf(rvv + cnp[cc]     - 2.0f * v0, 0.0f)));
                        v1 = __expf(sqrtf(fmaxf(rvv + cnp[cc + 1] - 2.0f * v1, 0.0f)));
                    } else if (EPI == 2) {
                        v0 = fmaxf(v0, 0.0f);
                        v1 = fmaxf(v1, 0.0f);
                    } else if (EPI == 3) {
                        v0 /= rvv; v1 /= rvv;
                    }
                    if (ROUND) { v0 = to_tf32(v0); v1 = to_tf32(v1); }
                    if (EPI == 1)
                        atomicAdd(&sum[z * Mtot + blockIdx.y * 128 + r], v0 + v1);
                    *(float2*)(CbaseH + (long long)r * N + cc) = make_float2(v0, v1);
                }
            }
        }
    }
#endif
}

// ---------------- reductions ----------------
__device__ __forceinline__ float warpReduceSum(float v) {
    v += __shfl_xor_sync(0xffffffffu, v, 16);
    v += __shfl_xor_sync(0xffffffffu, v, 8);
    v += __shfl_xor_sync(0xffffffffu, v, 4);
    v += __shfl_xor_sync(0xffffffffu, v, 2);
    v += __shfl_xor_sync(0xffffffffu, v, 1);
    return v;
}
__device__ __forceinline__ float blockAllReduceSum(float v, float* sh) {
    int lane = threadIdx.x & 31, wid = threadIdx.x >> 5;
    v = warpReduceSum(v);
    if (lane == 0) sh[wid] = v;
    __syncthreads();
    int nw = blockDim.x >> 5;
    float t = (lane < nw) ? sh[lane] : 0.0f;
    t = warpReduceSum(t);
    __syncthreads();
    return t;
}

// ---------------- tf32 pre-round ----------------
__global__ __launch_bounds__(256)
void round_kernel(const float* __restrict__ in, float* __restrict__ out, int n4)
{
    int i = blockIdx.x * 256 + threadIdx.x;
    if (i < n4) {
        float4 v = *(const float4*)(in + 4 * (long long)i);
        v.x = to_tf32(v.x); v.y = to_tf32(v.y);
        v.z = to_tf32(v.z); v.w = to_tf32(v.w);
        *(float4*)(out + 4 * (long long)i) = v;
    }
}

// ---------------- fp32 transpose + tf32 round ----------------
__global__ __launch_bounds__(256)
void transpose_kernel(const float* __restrict__ in, float* __restrict__ out,
                      int R, int C)
{
    __shared__ float t[32][33];
    int bx = blockIdx.x * 32, by = blockIdx.y * 32;
    int x = bx + threadIdx.x;
#pragma unroll
    for (int j = 0; j < 32; j += 8)
        t[threadIdx.y + j][threadIdx.x] = in[(long long)(by + threadIdx.y + j) * C + x];
    __syncthreads();
    int x2 = by + threadIdx.x;
#pragma unroll
    for (int j = 0; j < 32; j += 8)
        out[(long long)(bx + threadIdx.y + j) * R + x2] = to_tf32(t[threadIdx.x][threadIdx.y + j]);
}

// ---------------- row squared-norm ----------------
__global__ __launch_bounds__(128)
void rownorm2_kernel(const float* __restrict__ X, float* __restrict__ out)
{
    __shared__ float sh[32];
    long long row = blockIdx.x;
    const float* x = X + row * DD;
    float4 v = *(const float4*)(x + threadIdx.x * 4);
    float s = v.x * v.x + v.y * v.y + v.z * v.z + v.w * v.w;
    s = blockAllReduceSum(s, sh);
    if (threadIdx.x == 0) out[row] = s;
}

// ---------------- LayerNorm over D=512 (+ optional residual / tf32 round) ---
__global__ __launch_bounds__(128)
void layernorm_kernel(const float* __restrict__ X, const float* __restrict__ G,
                      const float* __restrict__ Bv, const float* __restrict__ R,
                      float* __restrict__ O, int rnd)
{
    __shared__ float sh[32];
    long long row = blockIdx.x;
    int c = threadIdx.x * 4;
    float4 v = *(const float4*)(X + row * DD + c);

    float s = v.x + v.y + v.z + v.w;
    s = blockAllReduceSum(s, sh);
    float mu = s * (1.0f / DD);

    float d0 = v.x - mu, d1 = v.y - mu, d2 = v.z - mu, d3 = v.w - mu;
    float s2 = d0 * d0 + d1 * d1 + d2 * d2 + d3 * d3;
    s2 = blockAllReduceSum(s2, sh);
    float inv = rsqrtf(s2 * (1.0f / DD) + 1e-5f);

    float4 gg = *(const float4*)(G + c);
    float4 bb = *(const float4*)(Bv + c);
    float4 o;
    o.x = d0 * inv * gg.x + bb.x;
    o.y = d1 * inv * gg.y + bb.y;
    o.z = d2 * inv * gg.z + bb.z;
    o.w = d3 * inv * gg.w + bb.w;
    if (R) {
        float4 rr = *(const float4*)(R + row * DD + c);
        o.x += rr.x; o.y += rr.y; o.z += rr.z; o.w += rr.w;
    }
    if (rnd) {
        o.x = to_tf32(o.x); o.y = to_tf32(o.y);
        o.z = to_tf32(o.z); o.w = to_tf32(o.w);
    }
    *(float4*)(O + row * DD + c) = o;
}

// ======================================================================
#define SMEM_BYTES 98304   // 2 x 48KB ring -> 2 CTAs/SM

extern "C" void kernel_launch(void* const* d_in, const int* in_sizes, int n_in,
                              void* d_out, int out_size)
{
    (void)in_sizes; (void)n_in; (void)out_size;
    const float* x   = (const float*)d_in[0];
    const float* src = (const float*)d_in[1];
    const float* Wq  = (const float*)d_in[2];
    const float* Wk  = (const float*)d_in[3];
    const float* Wv  = (const float*)d_in[4];
    const float* Wm  = (const float*)d_in[5];
    const float* W1  = (const float*)d_in[6];
    const float* W2  = (const float*)d_in[7];
    const float* g1  = (const float*)d_in[8];
    const float* b1  = (const float*)d_in[9];
    const float* g2  = (const float*)d_in[10];
    const float* b2  = (const float*)d_in[11];
    float* out = (float*)d_out;

    float *q, *k, *vT, *q2, *k2, *ssum, *sc, *msg, *mw, *mln, *hid, *ffn, *wt, *xr, *srcr;
    cudaGetSymbolAddress((void**)&q,    g_q);
    cudaGetSymbolAddress((void**)&k,    g_k);
    cudaGetSymbolAddress((void**)&vT,   g_vT);
    cudaGetSymbolAddress((void**)&q2,   g_q2);
    cudaGetSymbolAddress((void**)&k2,   g_k2);
    cudaGetSymbolAddress((void**)&ssum, g_ssum);
    cudaGetSymbolAddress((void**)&sc,   g_s);
    cudaGetSymbolAddress((void**)&msg,  g_msg);
    cudaGetSymbolAddress((void**)&mw,   g_mw);
    cudaGetSymbolAddress((void**)&mln,  g_mln);
    cudaGetSymbolAddress((void**)&hid,  g_hid);
    cudaGetSymbolAddress((void**)&ffn,  g_ffn);
    cudaGetSymbolAddress((void**)&wt,   g_wt);
    cudaGetSymbolAddress((void**)&xr,   g_xr);
    cudaGetSymbolAddress((void**)&srcr, g_srcr);

    float* WqT = wt;
    float* WkT = wt + DD * DD;
    float* WvT = wt + 2 * DD * DD;
    float* WmT = wt + 3 * DD * DD;
    float* W1T = wt + 4 * DD * DD;
    float* W2T = wt + 8 * DD * DD;

    cudaFuncSetAttribute(tc_gemm<0,0,0>, cudaFuncAttributeMaxDynamicSharedMemorySize, SMEM_BYTES);
    cudaFuncSetAttribute(tc_gemm<0,0,1>, cudaFuncAttributeMaxDynamicSharedMemorySize, SMEM_BYTES);
    cudaFuncSetAttribute(tc_gemm<1,0,1>, cudaFuncAttributeMaxDynamicSharedMemorySize, SMEM_BYTES);
    cudaFuncSetAttribute(tc_gemm<2,1,1>, cudaFuncAttributeMaxDynamicSharedMemorySize, SMEM_BYTES);
    cudaFuncSetAttribute(tc_gemm<3,0,1>, cudaFuncAttributeMaxDynamicSharedMemorySize, SMEM_BYTES);

    // 0. pre-round inputs, transpose weights, zero row-sum accumulator
    round_kernel<<<(NB * LQ * DD / 4 + 255) / 256,   256>>>(x,   xr,   NB * LQ * DD / 4);
    round_kernel<<<(NB * SSEQ * DD / 4 + 255) / 256, 256>>>(src, srcr, NB * SSEQ * DD / 4);
    transpose_kernel<<<dim3(16, 16), dim3(32, 8)>>>(Wq, WqT, DD, DD);
    transpose_kernel<<<dim3(16, 16), dim3(32, 8)>>>(Wk, WkT, DD, DD);
    transpose_kernel<<<dim3(16, 16), dim3(32, 8)>>>(Wv, WvT, DD, DD);
    transpose_kernel<<<dim3(16, 16), dim3(32, 8)>>>(Wm, WmT, DD, DD);
    transpose_kernel<<<dim3(32, 32), dim3(32, 8)>>>(W1, W1T, 2 * DD, 2 * DD);
    transpose_kernel<<<dim3(16, 32), dim3(32, 8)>>>(W2, W2T, 2 * DD, DD);
    cudaMemsetAsync(ssum, 0, NB * LQ * sizeof(float));

    // 1. projections
    tc_gemm<0,0,1><<<dim3(2, 64, 1),  256, SMEM_BYTES>>>(xr,   nullptr, WqT, q, DD, DD, DD, DD, 0, 0, 0, nullptr, nullptr, nullptr);
    tc_gemm<0,0,1><<<dim3(2, 256, 1), 256, SMEM_BYTES>>>(srcr, nullptr, WkT, k, DD, DD, DD, DD, 0, 0, 0, nullptr, nullptr, nullptr);
    tc_gemm<0,0,1><<<dim3(SSEQ / 256, DD / 128, NB), 256, SMEM_BYTES>>>(
        WvT, nullptr, srcr, vT, SSEQ, DD, DD, DD,
        0, (long long)SSEQ * DD, (long long)DD * SSEQ, nullptr, nullptr, nullptr);

    // 2. squared row norms (on rounded q,k)
    rownorm2_kernel<<<NB * LQ,   128>>>(q, q2);
    rownorm2_kernel<<<NB * SSEQ, 128>>>(k, k2);

    // 3. P_un = exp(sqrt(max(q2 + k2 - 2 q.k, 0))); row sums accumulated atomically
    tc_gemm<1,0,1><<<dim3(SSEQ / 256, LQ / 128, NB), 256, SMEM_BYTES>>>(
        q, nullptr, k, sc, SSEQ, DD, DD, DD,
        (long long)LQ * DD, (long long)SSEQ * DD, (long long)LQ * SSEQ, q2, k2, ssum);

    // 4. message = (P_un @ v) / rowsum
    tc_gemm<3,0,1><<<dim3(2, LQ / 128, NB), 256, SMEM_BYTES>>>(
        sc, nullptr, vT, msg, DD, SSEQ, SSEQ, SSEQ,
        (long long)LQ * SSEQ, (long long)DD * SSEQ, (long long)LQ * DD, ssum, nullptr, nullptr);

    // 5. mw = message @ Wm ; mln = LN(mw) rounded
    tc_gemm<0,0,0><<<dim3(2, 64, 1), 256, SMEM_BYTES>>>(msg, nullptr, WmT, mw, DD, DD, DD, DD, 0, 0, 0, nullptr, nullptr, nullptr);
    layernorm_kernel<<<NB * LQ, 128>>>(mw, g1, b1, nullptr, mln, 1);

    // 6. hid = relu([x, mln] @ W1), rounded
    tc_gemm<2,1,1><<<dim3(4, 64, 1), 256, SMEM_BYTES>>>(xr, mln, W1T, hid, 2 * DD, 2 * DD, DD, 2 * DD, 0, 0, 0, nullptr, nullptr, nullptr);

    // 7. ffn = hid @ W2
    tc_gemm<0,0,0><<<dim3(2, 64, 1), 256, SMEM_BYTES>>>(hid, nullptr, W2T, ffn, DD, 2 * DD, 2 * DD, 2 * DD, 0, 0, 0, nullptr, nullptr, nullptr);

    // 8. out = x + LN(ffn)
    layernorm_kernel<<<NB * LQ, 128>>>(ffn, g2, b2, x, out, 0);
}

// round 10
// speedup vs baseline: 5.1227x; 1.5276x over previous
#include <cuda_runtime.h>
#include <cuda_fp16.h>
#include <cstdint>

// Problem dims (fixed)
#define NB   8
#define LQ   1024
#define SSEQ 4096
#define DD   512

#ifndef __CUDA_ARCH_SPECIFIC__
#define __CUDA_ARCH_SPECIFIC__ 0
#endif
#if defined(__CUDA_ARCH_FEAT_SM103_ALL) || defined(__CUDA_ARCH_FEAT_SM100_ALL) || (__CUDA_ARCH_SPECIFIC__ >= 1000)
#define HAS_TCGEN05 1
#else
#define HAS_TCGEN05 0
#endif

// ---------------- static device scratch (no allocations allowed) ----------------
// fp16 operand buffers
static __device__ __half g_q  [NB * LQ * DD];
static __device__ __half g_k  [NB * SSEQ * DD];
static __device__ __half g_vT [NB * DD * SSEQ];
static __device__ __half g_s  [NB * LQ * SSEQ];       // exp(dist-12), unnormalized
static __device__ __half g_msg[NB * LQ * DD];
static __device__ __half g_mln[NB * LQ * DD];
static __device__ __half g_hid[NB * LQ * 2 * DD];
static __device__ __half g_xr [NB * LQ * DD];
static __device__ __half g_srcr[NB * SSEQ * DD];
static __device__ __half g_wth[4 * DD * DD + 4 * DD * DD + 2 * DD * DD]; // WqT..WmT, W1T, W2T
// fp32 buffers
static __device__ float g_q2 [NB * LQ];
static __device__ float g_k2 [NB * SSEQ];
static __device__ float g_ssum[NB * LQ];
static __device__ float g_mw [NB * LQ * DD];
static __device__ float g_ffn[NB * LQ * DD];

// ======================= PTX helpers =======================
__device__ __forceinline__ uint32_t smem_u32(const void* p) {
    uint32_t a;
    asm("{ .reg .u64 t; cvta.to.shared.u64 t, %1; cvt.u32.u64 %0, t; }" : "=r"(a) : "l"(p));
    return a;
}
#define CP_ASYNC16(dst, src) \
    asm volatile("cp.async.cg.shared.global [%0], [%1], 16;" :: "r"(dst), "l"(src) : "memory")
#define CP_COMMIT() asm volatile("cp.async.commit_group;" ::: "memory")
#define CP_WAIT1()  asm volatile("cp.async.wait_group 1;" ::: "memory")
#define CP_WAIT0()  asm volatile("cp.async.wait_group 0;" ::: "memory")

#if HAS_TCGEN05
__device__ __forceinline__ uint32_t elect_one() {
    uint32_t pred;
    asm volatile("{\n\t.reg .pred p;\n\telect.sync _|p, 0xFFFFFFFF;\n\t"
                 "selp.b32 %0, 1, 0, p;\n\t}" : "=r"(pred));
    return pred;
}
#define MBAR_INIT(addr, cnt) \
    asm volatile("mbarrier.init.shared.b64 [%0], %1;" :: "r"(addr), "r"(cnt) : "memory")
#define MBAR_INVAL(addr) \
    asm volatile("mbarrier.inval.shared.b64 [%0];" :: "r"(addr) : "memory")
__device__ __forceinline__ void mbar_wait(uint32_t addr, uint32_t parity) {
    uint32_t done;
    asm volatile("{\n\t.reg .pred p;\n\t"
                 "mbarrier.try_wait.parity.acquire.cta.shared::cta.b64 p, [%1], %2;\n\t"
                 "selp.b32 %0, 1, 0, p;\n\t}" : "=r"(done) : "r"(addr), "r"(parity) : "memory");
    if (!done) {
        asm volatile("{\n\t.reg .pred P1;\n\t"
                     "W_%=:\n\t"
                     "mbarrier.try_wait.parity.acquire.cta.shared::cta.b64 P1, [%0], %1, 0x989680;\n\t"
                     "@P1 bra.uni D_%=;\n\t"
                     "bra.uni W_%=;\n\t"
                     "D_%=:\n\t}" :: "r"(addr), "r"(parity) : "memory");
    }
}
#define TC_ALLOC(smem_addr, n) \
    asm volatile("tcgen05.alloc.cta_group::1.sync.aligned.shared::cta.b32 [%0], %1;" \
                 :: "r"(smem_addr), "r"(n) : "memory")
#define TC_DEALLOC(tmem, n) \
    asm volatile("tcgen05.dealloc.cta_group::1.sync.aligned.b32 %0, %1;" :: "r"(tmem), "r"(n))
#define TC_RELINQ() \
    asm volatile("tcgen05.relinquish_alloc_permit.cta_group::1.sync.aligned;")
#define TC_COMMIT(mbar) \
    asm volatile("tcgen05.commit.cta_group::1.mbarrier::arrive::one.shared::cluster.b64 [%0];" \
                 :: "r"(mbar) : "memory")
#define TC_FENCE_AFTER() asm volatile("tcgen05.fence::after_thread_sync;" ::: "memory")
#define TC_WAIT_LD()     asm volatile("tcgen05.wait::ld.sync.aligned;" ::: "memory")
#define FENCE_ASYNC()    asm volatile("fence.proxy.async.shared::cta;" ::: "memory")

// kind::f16 MMA (fp16 inputs, fp32 accum), zero disable-lane mask
__device__ __forceinline__ void mma_f16_ss(uint32_t d, uint64_t a, uint64_t b,
                                           uint32_t idesc, uint32_t en) {
    asm volatile("{\n\t.reg .pred p;\n\tsetp.ne.u32 p, %4, 0;\n\t"
                 "tcgen05.mma.cta_group::1.kind::f16 [%0], %1, %2, %3, {%5,%5,%5,%5}, p;\n\t}"
                 :: "r"(d), "l"(a), "l"(b), "r"(idesc), "r"(en), "r"(0u) : "memory");
}
__device__ __forceinline__ void tmem_ld_x32(uint32_t* r, uint32_t addr) {
    asm volatile(
        "tcgen05.ld.sync.aligned.32x32b.x32.b32 "
        "{%0,%1,%2,%3,%4,%5,%6,%7,%8,%9,%10,%11,%12,%13,%14,%15,"
        "%16,%17,%18,%19,%20,%21,%22,%23,%24,%25,%26,%27,%28,%29,%30,%31}, [%32];"
        : "=r"(r[0]), "=r"(r[1]), "=r"(r[2]), "=r"(r[3]), "=r"(r[4]), "=r"(r[5]),
          "=r"(r[6]), "=r"(r[7]), "=r"(r[8]), "=r"(r[9]), "=r"(r[10]), "=r"(r[11]),
          "=r"(r[12]), "=r"(r[13]), "=r"(r[14]), "=r"(r[15]), "=r"(r[16]), "=r"(r[17]),
          "=r"(r[18]), "=r"(r[19]), "=r"(r[20]), "=r"(r[21]), "=r"(r[22]), "=r"(r[23]),
          "=r"(r[24]), "=r"(r[25]), "=r"(r[26]), "=r"(r[27]), "=r"(r[28]), "=r"(r[29]),
          "=r"(r[30]), "=r"(r[31])
        : "r"(addr));
}
__device__ __forceinline__ uint32_t sw128(uint32_t b) { return b ^ ((b >> 3) & 0x70); }
static __device__ __forceinline__ uint64_t make_desc(uint32_t addr) {
    const uint64_t base = (uint64_t(2) << 61) | (uint64_t(1) << 46)
                        | (uint64_t(64) << 32) | (uint64_t(1) << 16);
    return base | ((uint64_t)(addr >> 4) & 0x3FFF);
}
// idesc kind::f16: dtype=F32(1<<4), atype=btype=FP16(0), N=128, M=128
#define IDESC_F16 ((1u << 4) | ((128u / 8u) << 17) | ((128u / 16u) << 24))
#endif  // HAS_TCGEN05

// ======================================================================
// NT GEMM: C[M,N] = A[M,K] * Bt[N,K]^T; fp16 operands, fp32 accumulate.
// CTA tile 128(M) x 256(N), K staged in chunks of 64 (row = 64 halfs = 128B,
// SW128). 2-slot ring (slot = A 16KB + B0 16KB + B1 16KB) -> 2 CTAs/SM.
// cp.async loader, per stage: 8 MMA dispatches (4 K16-steps x 2 N-halves).
// EPI: 0 none, 1 exp(sqrt(max(rn+cn-2acc,0))-12) + atomic row-sum,
//      2 relu, 3 divide by rn[row].
// OUTH: 1 -> output fp16, 0 -> fp32.
// DUAL: A logical K = 2*512 (halfs), first half gA, second gA2.
// ======================================================================
template<int EPI, int DUAL, int OUTH>
__global__ __launch_bounds__(256)
void tc_gemm(const __half* __restrict__ gA, const __half* __restrict__ gA2,
             const __half* __restrict__ gB, void* __restrict__ gC,
             int N, int K, int lda, int ldb,
             long long sA, long long sB, long long sC,
             const float* __restrict__ rn, const float* __restrict__ cn,
             float* __restrict__ sum)
{
    extern __shared__ __align__(1024) char dyn_smem[];

    const int tid = threadIdx.x;
    const int wid = tid >> 5, lane = tid & 31;

    const long long z = blockIdx.z;
    const __half* Abase  = gA + z * sA + (long long)blockIdx.y * 128 * lda;
    const __half* A2base = DUAL ? (gA2 + (long long)blockIdx.y * 128 * lda) : nullptr;
    const __half* Bbase  = gB + z * sB + (long long)blockIdx.x * 256 * ldb;
    const long long Coff = z * sC + (long long)blockIdx.y * 128 * N + blockIdx.x * 256;
    const int Mtot = gridDim.y * 128;

#if HAS_TCGEN05
    __shared__ uint32_t s_tmem[1];
    __shared__ __align__(8) uint64_t s_mbar[2];

    const uint32_t smem_base = smem_u32(dyn_smem);
    const uint32_t mbar_base = smem_u32(&s_mbar[0]);

    if (wid == 0) {
        TC_ALLOC(smem_u32(s_tmem), 256);
        TC_RELINQ();
    }
    if (tid == 0) { MBAR_INIT(mbar_base, 1); MBAR_INIT(mbar_base + 8, 1); }
    __syncthreads();
    const uint32_t tmem = s_tmem[0];

    // loader geometry: rows of 64 halfs = 128B, SW128; 16B = 8 halfs
    const int r0 = tid >> 3, c0 = tid & 7;

    auto cp_stage = [&](int s) {
        const int slot = s & 1;
        const uint32_t sbase = smem_base + slot * 49152;
        const int k0 = s * 64;
        const __half* Ap = DUAL ? (k0 < 512 ? Abase + k0 : A2base + (k0 - 512)) : (Abase + k0);
        const __half* Bp = Bbase + k0;
#pragma unroll
        for (int j = 0; j < 4; j++) {
            int row = r0 + j * 32;
            CP_ASYNC16(sbase + sw128((uint32_t)(row * 128 + c0 * 16)),
                       Ap + (long long)row * lda + c0 * 8);
        }
#pragma unroll
        for (int j = 0; j < 8; j++) {
            int row = r0 + j * 32;                 // 0..255
            uint32_t off = (j < 4) ? (16384u + sw128((uint32_t)(row * 128 + c0 * 16)))
                                   : (32768u + sw128((uint32_t)((row - 128) * 128 + c0 * 16)));
            CP_ASYNC16(sbase + off, Bp + (long long)row * ldb + c0 * 8);
        }
        CP_COMMIT();
    };

    const int nst = K / 64;                        // 8 / 16 / 64
    cp_stage(0);
    cp_stage(1);
    for (int s = 0; s < nst; s++) {
        const int slot = s & 1;
        if (s == nst - 1) CP_WAIT0(); else CP_WAIT1();
        __syncthreads();
        if (wid == 0) {
            FENCE_ASYNC();
            if (elect_one()) {
                uint32_t aAddr = smem_base + slot * 49152;
                uint64_t ad  = make_desc(aAddr);
                uint64_t bd0 = make_desc(aAddr + 16384);
                uint64_t bd1 = make_desc(aAddr + 32768);
#pragma unroll
                for (int st = 0; st < 4; st++) {   // 4 x K16 per stage
                    uint32_t en = (s > 0 || st > 0) ? 1u : 0u;
                    mma_f16_ss(tmem,       ad + st * 2, bd0 + st * 2, IDESC_F16, en);
                    mma_f16_ss(tmem + 128, ad + st * 2, bd1 + st * 2, IDESC_F16, en);
                }
                TC_COMMIT(mbar_base + slot * 8);
            }
        }
        if (s + 2 < nst) {
            mbar_wait(mbar_base + slot * 8, (s >> 1) & 1);
            cp_stage(s + 2);
        }
    }
    {
        const int L = nst - 1;
        mbar_wait(mbar_base + (L & 1) * 8, (L >> 1) & 1);
    }
    TC_FENCE_AFTER();

    // ---------------- epilogue ----------------
    float* stg = (float*)dyn_smem;                 // [128][33] staging
    float rv = 0.0f, rinv = 0.0f, psum = 0.0f, cnv = 0.0f;
    if (wid < 4) {
        int rowg = (int)(z * Mtot) + blockIdx.y * 128 + wid * 32 + lane;
        if (EPI == 1) rv = rn[rowg];
        if (EPI == 3) rinv = 1.0f / rn[rowg];
    }

#pragma unroll
    for (int ch = 0; ch < 8; ch++) {
        if (wid < 4) {
            uint32_t r[32];
            tmem_ld_x32(r, tmem + ch * 32);
            TC_WAIT_LD();
            if (EPI == 1) cnv = cn[z * N + (long long)blockIdx.x * 256 + ch * 32 + lane];
            int row = wid * 32 + lane;
#pragma unroll
            for (int c = 0; c < 32; c++) {
                float v = __uint_as_float(r[c]);
                if (EPI == 1) {
                    float cc = __shfl_sync(0xffffffffu, cnv, c);
                    v = __expf(sqrtf(fmaxf(rv + cc - 2.0f * v, 0.0f)) - 12.0f);
                    v = __half2float(__float2half_rn(v));   // sum the STORED value
                    psum += v;
                } else if (EPI == 2) {
                    v = fmaxf(v, 0.0f);
                } else if (EPI == 3) {
                    v *= rinv;
                }
                stg[row * 33 + c] = v;
            }
        }
        __syncthreads();
#pragma unroll
        for (int it = 0; it < 16; it++) {
            int row = wid + it * 8;
            long long idx = Coff + (long long)row * N + ch * 32 + lane;
            float v = stg[row * 33 + lane];
            if (OUTH) ((__half*)gC)[idx] = __float2half_rn(v);
            else      ((float*)gC)[idx] = v;
        }
        __syncthreads();
    }
    if (EPI == 1 && wid < 4) {
        int rowg = (int)(z * Mtot) + blockIdx.y * 128 + wid * 32 + lane;
        atomicAdd(&sum[rowg], psum);
    }

    if (tid == 0) { MBAR_INVAL(mbar_base); MBAR_INVAL(mbar_base + 8); }
    __syncthreads();
    if (wid == 0) TC_DEALLOC(tmem, 256);

#else
    // ---- trivial scalar fallback (compute_103 pass only; never selected) ----
    for (int idx = tid; idx < 128 * 256; idx += 256) {
        int row = idx >> 8, col = idx & 255;
        float acc = 0.0f;
        for (int kk = 0; kk < K; kk++) {
            const __half* Ap = DUAL ? (kk < 512 ? Abase + kk : A2base + (kk - 512)) : (Abase + kk);
            float a = __half2float(Ap[(long long)row * lda]);
            float b = __half2float(Bbase[(long long)col * ldb + kk]);
            acc += a * b;
        }
        float v = acc;
        if (EPI == 1) {
            float rr = rn[z * Mtot + blockIdx.y * 128 + row];
            float cc = cn[z * N + blockIdx.x * 256 + col];
            v = __expf(sqrtf(fmaxf(rr + cc - 2.0f * v, 0.0f)) - 12.0f);
            v = __half2float(__float2half_rn(v));
            atomicAdd(&sum[z * Mtot + blockIdx.y * 128 + row], v);
        } else if (EPI == 2) v = fmaxf(v, 0.0f);
        else if (EPI == 3) v /= rn[z * Mtot + blockIdx.y * 128 + row];
        long long o = Coff + (long long)row * N + col;
        if (OUTH) ((__half*)gC)[o] = __float2half_rn(v);
        else      ((float*)gC)[o] = v;
    }
#endif
}

// ---------------- reductions ----------------
__device__ __forceinline__ float warpReduceSum(float v) {
    v += __shfl_xor_sync(0xffffffffu, v, 16);
    v += __shfl_xor_sync(0xffffffffu, v, 8);
    v += __shfl_xor_sync(0xffffffffu, v, 4);
    v += __shfl_xor_sync(0xffffffffu, v, 2);
    v += __shfl_xor_sync(0xffffffffu, v, 1);
    return v;
}
__device__ __forceinline__ float blockAllReduceSum(float v, float* sh) {
    int lane = threadIdx.x & 31, wid = threadIdx.x >> 5;
    v = warpReduceSum(v);
    if (lane == 0) sh[wid] = v;
    __syncthreads();
    int nw = blockDim.x >> 5;
    float t = (lane < nw) ? sh[lane] : 0.0f;
    t = warpReduceSum(t);
    __syncthreads();
    return t;
}

// ---------------- fp32 -> fp16 convert ----------------
__global__ __launch_bounds__(256)
void convert_kernel(const float* __restrict__ in, __half* __restrict__ out, int n4)
{
    int i = blockIdx.x * 256 + threadIdx.x;
    if (i < n4) {
        float4 v = *(const float4*)(in + 4 * (long long)i);
        __half2 h0 = __floats2half2_rn(v.x, v.y);
        __half2 h1 = __floats2half2_rn(v.z, v.w);
        *(__half2*)(out + 4 * (long long)i)     = h0;
        *(__half2*)(out + 4 * (long long)i + 2) = h1;
    }
}

// ---------------- fp32 transpose -> fp16 ----------------
__global__ __launch_bounds__(256)
void transpose_kernel(const float* __restrict__ in, __half* __restrict__ out,
                      int R, int C)
{
    __shared__ float t[32][33];
    int bx = blockIdx.x * 32, by = blockIdx.y * 32;
    int x = bx + threadIdx.x;
#pragma unroll
    for (int j = 0; j < 32; j += 8)
        t[threadIdx.y + j][threadIdx.x] = in[(long long)(by + threadIdx.y + j) * C + x];
    __syncthreads();
    int x2 = by + threadIdx.x;
#pragma unroll
    for (int j = 0; j < 32; j += 8)
        out[(long long)(bx + threadIdx.y + j) * R + x2] = __float2half_rn(t[threadIdx.x][threadIdx.y + j]);
}

// ---------------- row squared-norm over D=512 fp16 rows ----------------
__global__ __launch_bounds__(128)
void rownorm2_kernel(const __half* __restrict__ X, float* __restrict__ out)
{
    __shared__ float sh[32];
    long long row = blockIdx.x;
    const __half* x = X + row * DD;
    // 128 threads x 4 halfs
    __half2 h0 = *(const __half2*)(x + threadIdx.x * 4);
    __half2 h1 = *(const __half2*)(x + threadIdx.x * 4 + 2);
    float2 f0 = __half22float2(h0), f1 = __half22float2(h1);
    float s = f0.x * f0.x + f0.y * f0.y + f1.x * f1.x + f1.y * f1.y;
    s = blockAllReduceSum(s, sh);
    if (threadIdx.x == 0) out[row] = s;
}

// ---------------- LayerNorm over D=512 (fp32 in; fp16 or fp32+res out) -----
template<int OUTH>
__global__ __launch_bounds__(128)
void layernorm_kernel(const float* __restrict__ X, const float* __restrict__ G,
                      const float* __restrict__ Bv, const float* __restrict__ R,
                      void* __restrict__ O)
{
    __shared__ float sh[32];
    long long row = blockIdx.x;
    int c = threadIdx.x * 4;
    float4 v = *(const float4*)(X + row * DD + c);

    float s = v.x + v.y + v.z + v.w;
    s = blockAllReduceSum(s, sh);
    float mu = s * (1.0f / DD);

    float d0 = v.x - mu, d1 = v.y - mu, d2 = v.z - mu, d3 = v.w - mu;
    float s2 = d0 * d0 + d1 * d1 + d2 * d2 + d3 * d3;
    s2 = blockAllReduceSum(s2, sh);
    float inv = rsqrtf(s2 * (1.0f / DD) + 1e-5f);

    float4 gg = *(const float4*)(G + c);
    float4 bb = *(const float4*)(Bv + c);
    float o0 = d0 * inv * gg.x + bb.x;
    float o1 = d1 * inv * gg.y + bb.y;
    float o2 = d2 * inv * gg.z + bb.z;
    float o3 = d3 * inv * gg.w + bb.w;
    if (R) {
        float4 rr = *(const float4*)(R + row * DD + c);
        o0 += rr.x; o1 += rr.y; o2 += rr.z; o3 += rr.w;
    }
    if (OUTH) {
        __half* Oh = (__half*)O + row * DD + c;
        *(__half2*)(Oh)     = __floats2half2_rn(o0, o1);
        *(__half2*)(Oh + 2) = __floats2half2_rn(o2, o3);
    } else {
        *(float4*)((float*)O + row * DD + c) = make_float4(o0, o1, o2, o3);
    }
}

// ======================================================================
#define SMEM_BYTES 98304   // 2 x 48KB ring -> 2 CTAs/SM

extern "C" void kernel_launch(void* const* d_in, const int* in_sizes, int n_in,
                              void* d_out, int out_size)
{
    (void)in_sizes; (void)n_in; (void)out_size;
    const float* x   = (const float*)d_in[0];
    const float* src = (const float*)d_in[1];
    const float* Wq  = (const float*)d_in[2];
    const float* Wk  = (const float*)d_in[3];
    const float* Wv  = (const float*)d_in[4];
    const float* Wm  = (const float*)d_in[5];
    const float* W1  = (const float*)d_in[6];
    const float* W2  = (const float*)d_in[7];
    const float* g1  = (const float*)d_in[8];
    const float* b1  = (const float*)d_in[9];
    const float* g2  = (const float*)d_in[10];
    const float* b2  = (const float*)d_in[11];
    float* out = (float*)d_out;

    __half *q, *k, *vT, *sc, *msg, *mln, *hid, *xr, *srcr, *wth;
    float *q2, *k2, *ssum, *mw, *ffn;
    cudaGetSymbolAddress((void**)&q,    g_q);
    cudaGetSymbolAddress((void**)&k,    g_k);
    cudaGetSymbolAddress((void**)&vT,   g_vT);
    cudaGetSymbolAddress((void**)&sc,   g_s);
    cudaGetSymbolAddress((void**)&msg,  g_msg);
    cudaGetSymbolAddress((void**)&mln,  g_mln);
    cudaGetSymbolAddress((void**)&hid,  g_hid);
    cudaGetSymbolAddress((void**)&xr,   g_xr);
    cudaGetSymbolAddress((void**)&srcr, g_srcr);
    cudaGetSymbolAddress((void**)&wth,  g_wth);
    cudaGetSymbolAddress((void**)&q2,   g_q2);
    cudaGetSymbolAddress((void**)&k2,   g_k2);
    cudaGetSymbolAddress((void**)&ssum, g_ssum);
    cudaGetSymbolAddress((void**)&mw,   g_mw);
    cudaGetSymbolAddress((void**)&ffn,  g_ffn);

    __half* WqT = wth;
    __half* WkT = wth + DD * DD;
    __half* WvT = wth + 2 * DD * DD;
    __half* WmT = wth + 3 * DD * DD;
    __half* W1T = wth + 4 * DD * DD;
    __half* W2T = wth + 8 * DD * DD;

    cudaFuncSetAttribute(tc_gemm<0,0,1>, cudaFuncAttributeMaxDynamicSharedMemorySize, SMEM_BYTES);
    cudaFuncSetAttribute(tc_gemm<0,0,0>, cudaFuncAttributeMaxDynamicSharedMemorySize, SMEM_BYTES);
    cudaFuncSetAttribute(tc_gemm<1,0,1>, cudaFuncAttributeMaxDynamicSharedMemorySize, SMEM_BYTES);
    cudaFuncSetAttribute(tc_gemm<2,1,1>, cudaFuncAttributeMaxDynamicSharedMemorySize, SMEM_BYTES);
    cudaFuncSetAttribute(tc_gemm<3,0,1>, cudaFuncAttributeMaxDynamicSharedMemorySize, SMEM_BYTES);

    // 0. convert inputs to fp16, transpose weights to fp16, zero row sums
    convert_kernel<<<(NB * LQ * DD / 4 + 255) / 256,   256>>>(x,   xr,   NB * LQ * DD / 4);
    convert_kernel<<<(NB * SSEQ * DD / 4 + 255) / 256, 256>>>(src, srcr, NB * SSEQ * DD / 4);
    transpose_kernel<<<dim3(16, 16), dim3(32, 8)>>>(Wq, WqT, DD, DD);
    transpose_kernel<<<dim3(16, 16), dim3(32, 8)>>>(Wk, WkT, DD, DD);
    transpose_kernel<<<dim3(16, 16), dim3(32, 8)>>>(Wv, WvT, DD, DD);
    transpose_kernel<<<dim3(16, 16), dim3(32, 8)>>>(Wm, WmT, DD, DD);
    transpose_kernel<<<dim3(32, 32), dim3(32, 8)>>>(W1, W1T, 2 * DD, 2 * DD);
    transpose_kernel<<<dim3(16, 32), dim3(32, 8)>>>(W2, W2T, 2 * DD, DD);
    cudaMemsetAsync(ssum, 0, NB * LQ * sizeof(float));

    // 1. projections (fp16 out)
    tc_gemm<0,0,1><<<dim3(2, 64, 1),  256, SMEM_BYTES>>>(xr,   nullptr, WqT, q, DD, DD, DD, DD, 0, 0, 0, nullptr, nullptr, nullptr);
    tc_gemm<0,0,1><<<dim3(2, 256, 1), 256, SMEM_BYTES>>>(srcr, nullptr, WkT, k, DD, DD, DD, DD, 0, 0, 0, nullptr, nullptr, nullptr);
    tc_gemm<0,0,1><<<dim3(SSEQ / 256, DD / 128, NB), 256, SMEM_BYTES>>>(
        WvT, nullptr, srcr, vT, SSEQ, DD, DD, DD,
        0, (long long)SSEQ * DD, (long long)DD * SSEQ, nullptr, nullptr, nullptr);

    // 2. squared row norms (on fp16 q,k)
    rownorm2_kernel<<<NB * LQ,   128>>>(q, q2);
    rownorm2_kernel<<<NB * SSEQ, 128>>>(k, k2);

    // 3. P_un = exp(dist - 12) fp16; row sums accumulated atomically (shift cancels)
    tc_gemm<1,0,1><<<dim3(SSEQ / 256, LQ / 128, NB), 256, SMEM_BYTES>>>(
        q, nullptr, k, sc, SSEQ, DD, DD, DD,
        (long long)LQ * DD, (long long)SSEQ * DD, (long long)LQ * SSEQ, q2, k2, ssum);

    // 4. message = (P_un @ v) / rowsum  (fp16 out)
    tc_gemm<3,0,1><<<dim3(2, LQ / 128, NB), 256, SMEM_BYTES>>>(
        sc, nullptr, vT, msg, DD, SSEQ, SSEQ, SSEQ,
        (long long)LQ * SSEQ, (long long)DD * SSEQ, (long long)LQ * DD, ssum, nullptr, nullptr);

    // 5. mw = message @ Wm (fp32 out); mln = LN(mw) fp16
    tc_gemm<0,0,0><<<dim3(2, 64, 1), 256, SMEM_BYTES>>>(msg, nullptr, WmT, mw, DD, DD, DD, DD, 0, 0, 0, nullptr, nullptr, nullptr);
    layernorm_kernel<1><<<NB * LQ, 128>>>(mw, g1, b1, nullptr, mln);

    // 6. hid = relu([x, mln] @ W1) fp16
    tc_gemm<2,1,1><<<dim3(4, 64, 1), 256, SMEM_BYTES>>>(xr, mln, W1T, hid, 2 * DD, 2 * DD, DD, 2 * DD, 0, 0, 0, nullptr, nullptr, nullptr);

    // 7. ffn = hid @ W2 (fp32 out)
    tc_gemm<0,0,0><<<dim3(2, 64, 1), 256, SMEM_BYTES>>>(hid, nullptr, W2T, ffn, DD, 2 * DD, 2 * DD, 2 * DD, 0, 0, 0, nullptr, nullptr, nullptr);

    // 8. out = x + LN(ffn)   (residual uses ORIGINAL fp32 x)
    layernorm_kernel<0><<<NB * LQ, 128>>>(ffn, g2, b2, x, out);
}